// round 10
// baseline (speedup 1.0000x reference)
#include <cuda_runtime.h>

typedef unsigned long long ull;

// ---------------------------------------------------------------------------
// f32x2 packed FMA helpers
// ---------------------------------------------------------------------------
__device__ __forceinline__ ull ffma2(ull a, ull b, ull c) {
    ull d;
    asm("fma.rn.f32x2 %0, %1, %2, %3;" : "=l"(d) : "l"(a), "l"(b), "l"(c));
    return d;
}
__device__ __forceinline__ ull pack2(float lo, float hi) {
    ull d;
    asm("mov.b64 %0, {%1, %2};" : "=l"(d) : "f"(lo), "f"(hi));
    return d;
}
__device__ __forceinline__ float2 unpack2(ull v) {
    float2 r;
    asm("mov.b64 {%0, %1}, %2;" : "=f"(r.x), "=f"(r.y) : "l"(v));
    return r;
}

// ---------------------------------------------------------------------------
// Problem constants
// ---------------------------------------------------------------------------
#define B_    128
#define T_    20
#define C_    4
#define HW_   4096
#define D_    128

#define M_TOT (B_ * T_ * C_)   // 10240
#define K_TOT HW_              // 4096
#define N_TOT D_               // 128

#define KSPLIT 2
#define KSEG   (K_TOT / KSPLIT)   // 2048

// scratch: un-activated GEMM partials [split][M][128]
__device__ float g_part[KSPLIT * M_TOT * N_TOT];

// ---------------------------------------------------------------------------
// Kernel 1: fused noise-add + embedding GEMM (K-split partial sums)
//   grid (160, 2): blockIdx.x = m-tile, blockIdx.y = K segment.
// ---------------------------------------------------------------------------
#define BM   64
#define BK   16
#define APAD 66

__global__ __launch_bounds__(256, 3) void emb_kernel(
    const float* __restrict__ X, const float* __restrict__ N1,
    const float* __restrict__ N2, const float* __restrict__ W)
{
    __shared__ float As[2][BK][APAD];
    __shared__ float Bs[2][BK][N_TOT];

    const int tid = threadIdx.x;
    const int m0  = blockIdx.x * BM;
    const int ks0 = blockIdx.y * KSEG;
    const int rg  = tid >> 5;   // warp id = row group (8 rows)
    const int cg  = tid & 31;   // col group (4 cols)

    const int ar = tid >> 2;    // 0..63 row in tile
    const int af = tid & 3;     // 0..3  float4 within BK
    const long aBase = (long)(m0 + ar) * K_TOT + ks0 + af * 4;
    const int bk0 = tid >> 5;   // 0..7
    const int bc0 = tid & 31;
    const long bBase = (long)(ks0 + bk0) * N_TOT + bc0 * 4;

    float4 ax, an1, an2, bw0, bw1;
    ull acc[4][4];
#pragma unroll
    for (int p = 0; p < 4; p++)
#pragma unroll
        for (int j = 0; j < 4; j++) acc[p][j] = 0ull;

#define LOAD_TILE(kt) do {                                     \
        long off = aBase + (long)(kt) * BK;                    \
        ax  = *(const float4*)(X  + off);                      \
        an1 = *(const float4*)(N1 + off);                      \
        an2 = *(const float4*)(N2 + off);                      \
        long wo = bBase + (long)(kt) * BK * N_TOT;             \
        bw0 = *(const float4*)(W + wo);                        \
        bw1 = *(const float4*)(W + wo + 8 * N_TOT);            \
    } while (0)

#define STORE_TILE(bufi) do {                                              \
        As[bufi][af*4+0][ar] = ax.x + 1e-3f*an1.x + 1e-4f*an2.x;           \
        As[bufi][af*4+1][ar] = ax.y + 1e-3f*an1.y + 1e-4f*an2.y;           \
        As[bufi][af*4+2][ar] = ax.z + 1e-3f*an1.z + 1e-4f*an2.z;           \
        As[bufi][af*4+3][ar] = ax.w + 1e-3f*an1.w + 1e-4f*an2.w;           \
        *(float4*)&Bs[bufi][bk0    ][bc0*4] = bw0;                         \
        *(float4*)&Bs[bufi][bk0 + 8][bc0*4] = bw1;                         \
    } while (0)

    LOAD_TILE(0);
    STORE_TILE(0);
    __syncthreads();

    const int NT = KSEG / BK;  // 128
    for (int kt = 0; kt < NT; kt++) {
        const int buf = kt & 1;
        if (kt + 1 < NT) LOAD_TILE(kt + 1);
#pragma unroll
        for (int kk = 0; kk < BK; kk++) {
            float2 a0 = *(const float2*)&As[buf][kk][rg*8 + 0];
            float2 a1 = *(const float2*)&As[buf][kk][rg*8 + 2];
            float2 a2 = *(const float2*)&As[buf][kk][rg*8 + 4];
            float2 a3 = *(const float2*)&As[buf][kk][rg*8 + 6];
            float4 b  = *(const float4*)&Bs[buf][kk][cg*4];
            ull ap0 = pack2(a0.x, a0.y), ap1 = pack2(a1.x, a1.y);
            ull ap2 = pack2(a2.x, a2.y), ap3 = pack2(a3.x, a3.y);
            ull bp0 = pack2(b.x, b.x), bp1 = pack2(b.y, b.y);
            ull bp2 = pack2(b.z, b.z), bp3 = pack2(b.w, b.w);
            acc[0][0] = ffma2(ap0, bp0, acc[0][0]);
            acc[0][1] = ffma2(ap0, bp1, acc[0][1]);
            acc[0][2] = ffma2(ap0, bp2, acc[0][2]);
            acc[0][3] = ffma2(ap0, bp3, acc[0][3]);
            acc[1][0] = ffma2(ap1, bp0, acc[1][0]);
            acc[1][1] = ffma2(ap1, bp1, acc[1][1]);
            acc[1][2] = ffma2(ap1, bp2, acc[1][2]);
            acc[1][3] = ffma2(ap1, bp3, acc[1][3]);
            acc[2][0] = ffma2(ap2, bp0, acc[2][0]);
            acc[2][1] = ffma2(ap2, bp1, acc[2][1]);
            acc[2][2] = ffma2(ap2, bp2, acc[2][2]);
            acc[2][3] = ffma2(ap2, bp3, acc[2][3]);
            acc[3][0] = ffma2(ap3, bp0, acc[3][0]);
            acc[3][1] = ffma2(ap3, bp1, acc[3][1]);
            acc[3][2] = ffma2(ap3, bp2, acc[3][2]);
            acc[3][3] = ffma2(ap3, bp3, acc[3][3]);
        }
        if (kt + 1 < NT) {
            __syncthreads();
            STORE_TILE(buf ^ 1);
            __syncthreads();
        }
    }

    float* gp = g_part + (size_t)blockIdx.y * (M_TOT * N_TOT);
#pragma unroll
    for (int j = 0; j < 4; j++) {
        const int n = cg * 4 + j;
#pragma unroll
        for (int p = 0; p < 4; p++) {
            float2 v = unpack2(acc[p][j]);
            const int r = m0 + rg * 8 + 2 * p;
            gp[r * N_TOT + n]       = v.x;
            gp[(r + 1) * N_TOT + n] = v.y;
        }
    }
#undef LOAD_TILE
#undef STORE_TILE
}

// ---------------------------------------------------------------------------
// Mega kernel: per-batch fused (partial-combine + 2 axial blocks + decoder).
//   One block per b.  256 threads.  Everything resident in smem.
//   hsT / otT / osT are TRANSPOSED: [col][row], row-stride RP=82 (pad).
// ---------------------------------------------------------------------------
#define RP 82   // padded row stride (80 rows + 2)

#define MEGA_FLOATS (128*RP + 128*RP + 128*96 + 32*128 + 128 + 3*80*32 + 32*RP)
#define MEGA_BYTES  (MEGA_FLOATS * 4)

__global__ __launch_bounds__(256) void mega_kernel(
    const float* __restrict__ Wq,   // [2][2][128][32]
    const float* __restrict__ Wkv,  // [2][2][128][64]
    const float* __restrict__ Wout, // [2][2][32][128]
    const float* __restrict__ Bout, // [2][2][128]
    const float* __restrict__ Bemb, // [128]
    const float* __restrict__ Wd,   // [10240]
    const float* __restrict__ bd,   // [1]
    float* __restrict__ out)
{
    extern __shared__ float sm[];
    float* hsT = sm;                    // [128][RP]  h transposed
    float* otT = hsT + 128 * RP;        // [128][RP]  out_t transposed
    float* wp  = otT + 128 * RP;        // [128][96]  q|k|v proj weights
    float* wo  = wp  + 128 * 96;        // [32][128]
    float* bo  = wo  + 32 * 128;        // [128]
    float* qs  = bo  + 128;             // [80][32]
    float* ks  = qs  + 80 * 32;
    float* vs  = ks  + 80 * 32;
    float* osT = vs  + 80 * 32;         // [32][RP]

    const int tid = threadIdx.x;
    const int b   = blockIdx.x;

    // ---- combine GEMM partials + bias + leaky, transpose into smem ----
    {
        const float* p0 = g_part + (size_t)b * (T_ * C_ * D_);
        const float* p1 = g_part + (size_t)(M_TOT * N_TOT) + (size_t)b * (T_ * C_ * D_);
        for (int f = tid; f < 10240; f += 256) {
            int r = f >> 7, d = f & 127;
            float u = p0[f] + p1[f] + Bemb[d];
            hsT[d * RP + r] = (u > 0.f) ? u : 0.2f * u;
        }
    }
    __syncthreads();

    for (int blk = 0; blk < 2; blk++) {
        for (int axis = 0; axis < 2; axis++) {
            const int s = blk * 2 + axis;

            // ---- stage weights ----
            const float4* wq4  = (const float4*)(Wq  + s * 128 * 32);
            const float4* wkv4 = (const float4*)(Wkv + s * 128 * 64);
            for (int f = tid; f < 128 * 24; f += 256) {
                int d = f / 24, q4 = f - d * 24;
                float4 v = (q4 < 8) ? wq4[d * 8 + q4] : wkv4[d * 16 + (q4 - 8)];
                *(float4*)&wp[d * 96 + q4 * 4] = v;
            }
            const float4* wo4 = (const float4*)(Wout + s * 32 * 128);
            for (int f = tid; f < 1024; f += 256) ((float4*)wo)[f] = wo4[f];
            if (tid < 128) bo[tid] = Bout[s * 128 + tid];
            __syncthreads();

            // ---- qkv projection: 80 rows x 96 cols, thread tile 8x4 ----
            if (tid < 240) {
                const int rg = tid / 24;          // 0..9  (rows rg*8..+7)
                const int cg = tid - rg * 24;     // 0..23 (cols cg*4..+3)
                ull acc[4][4];
#pragma unroll
                for (int p = 0; p < 4; p++)
#pragma unroll
                    for (int j = 0; j < 4; j++) acc[p][j] = 0ull;

                const float* hb = &hsT[rg * 8];
                const float* wb = &wp[cg * 4];
#pragma unroll 4
                for (int d = 0; d < 128; d++) {
                    float2 a0 = *(const float2*)&hb[d * RP + 0];
                    float2 a1 = *(const float2*)&hb[d * RP + 2];
                    float2 a2 = *(const float2*)&hb[d * RP + 4];
                    float2 a3 = *(const float2*)&hb[d * RP + 6];
                    float4 w  = *(const float4*)&wb[d * 96];
                    ull ap0 = pack2(a0.x, a0.y), ap1 = pack2(a1.x, a1.y);
                    ull ap2 = pack2(a2.x, a2.y), ap3 = pack2(a3.x, a3.y);
                    ull bp0 = pack2(w.x, w.x), bp1 = pack2(w.y, w.y);
                    ull bp2 = pack2(w.z, w.z), bp3 = pack2(w.w, w.w);
                    acc[0][0] = ffma2(ap0, bp0, acc[0][0]);
                    acc[0][1] = ffma2(ap0, bp1, acc[0][1]);
                    acc[0][2] = ffma2(ap0, bp2, acc[0][2]);
                    acc[0][3] = ffma2(ap0, bp3, acc[0][3]);
                    acc[1][0] = ffma2(ap1, bp0, acc[1][0]);
                    acc[1][1] = ffma2(ap1, bp1, acc[1][1]);
                    acc[1][2] = ffma2(ap1, bp2, acc[1][2]);
                    acc[1][3] = ffma2(ap1, bp3, acc[1][3]);
                    acc[2][0] = ffma2(ap2, bp0, acc[2][0]);
                    acc[2][1] = ffma2(ap2, bp1, acc[2][1]);
                    acc[2][2] = ffma2(ap2, bp2, acc[2][2]);
                    acc[2][3] = ffma2(ap2, bp3, acc[2][3]);
                    acc[3][0] = ffma2(ap3, bp0, acc[3][0]);
                    acc[3][1] = ffma2(ap3, bp1, acc[3][1]);
                    acc[3][2] = ffma2(ap3, bp2, acc[3][2]);
                    acc[3][3] = ffma2(ap3, bp3, acc[3][3]);
                }
                const int which = cg >> 3;   // 0=q, 1=k, 2=v
                float* dst = (which == 0) ? qs : (which == 1) ? ks : vs;
                const int lj = (cg & 7) * 4;
#pragma unroll
                for (int p = 0; p < 4; p++) {
                    const int r0 = rg * 8 + 2 * p;
#pragma unroll
                    for (int jc = 0; jc < 4; jc++) {
                        float2 v = unpack2(acc[p][jc]);
                        dst[r0 * 32 + lj + jc]       = v.x;
                        dst[(r0 + 1) * 32 + lj + jc] = v.y;
                    }
                }
            }
            __syncthreads();

            // ---- attention core (640 tasks) ----
            for (int o = tid; o < 640; o += 256) {
                if (axis == 0) {
                    // attend over T: task = (c, h, t), keys t' = 0..19
                    const int t  = o % 20;
                    const int ch = o / 20;
                    const int c  = ch & 3, h = ch >> 2;
                    const int r  = t * 4 + c;
                    const float* qp = &qs[r * 32 + h * 4];
                    float p[20];
                    float mx = -1e30f;
#pragma unroll
                    for (int s2 = 0; s2 < 20; s2++) {
                        const float* kp = &ks[(s2 * 4 + c) * 32 + h * 4];
                        float d = (qp[0]*kp[0] + qp[1]*kp[1] + qp[2]*kp[2] + qp[3]*kp[3]) * 0.5f;
                        p[s2] = d;
                        mx = fmaxf(mx, d);
                    }
                    float sum = 0.f;
#pragma unroll
                    for (int s2 = 0; s2 < 20; s2++) { p[s2] = __expf(p[s2] - mx); sum += p[s2]; }
                    float inv = 1.f / sum;
                    float o0 = 0.f, o1 = 0.f, o2 = 0.f, o3 = 0.f;
#pragma unroll
                    for (int s2 = 0; s2 < 20; s2++) {
                        const float* vp = &vs[(s2 * 4 + c) * 32 + h * 4];
                        float w = p[s2] * inv;
                        o0 += w * vp[0]; o1 += w * vp[1]; o2 += w * vp[2]; o3 += w * vp[3];
                    }
                    osT[(h*4 + 0) * RP + r] = o0;
                    osT[(h*4 + 1) * RP + r] = o1;
                    osT[(h*4 + 2) * RP + r] = o2;
                    osT[(h*4 + 3) * RP + r] = o3;
                } else {
                    // attend over C: task = (t, h, cq), keys c' = 0..3
                    const int cq = o & 3;
                    const int h  = (o >> 2) & 7;
                    const int t  = o >> 5;
                    const int r  = t * 4 + cq;
                    const float* qp = &qs[r * 32 + h * 4];
                    float p[4];
                    float mx = -1e30f;
#pragma unroll
                    for (int s2 = 0; s2 < 4; s2++) {
                        const float* kp = &ks[(t * 4 + s2) * 32 + h * 4];
                        float d = (qp[0]*kp[0] + qp[1]*kp[1] + qp[2]*kp[2] + qp[3]*kp[3]) * 0.5f;
                        p[s2] = d;
                        mx = fmaxf(mx, d);
                    }
                    float sum = 0.f;
#pragma unroll
                    for (int s2 = 0; s2 < 4; s2++) { p[s2] = __expf(p[s2] - mx); sum += p[s2]; }
                    float inv = 1.f / sum;
                    float o0 = 0.f, o1 = 0.f, o2 = 0.f, o3 = 0.f;
#pragma unroll
                    for (int s2 = 0; s2 < 4; s2++) {
                        const float* vp = &vs[(t * 4 + s2) * 32 + h * 4];
                        float w = p[s2] * inv;
                        o0 += w * vp[0]; o1 += w * vp[1]; o2 += w * vp[2]; o3 += w * vp[3];
                    }
                    osT[(h*4 + 0) * RP + r] = o0;
                    osT[(h*4 + 1) * RP + r] = o1;
                    osT[(h*4 + 2) * RP + r] = o2;
                    osT[(h*4 + 3) * RP + r] = o3;
                }
            }
            __syncthreads();

            // ---- output projection: 80 rows x 128 cols, thread tile 8x8 ----
            if (tid < 160) {
                const int rg = tid >> 4;          // 0..9
                const int cg = tid & 15;          // cols cg*8..+7
                ull acc[4][8];
#pragma unroll
                for (int p = 0; p < 4; p++)
#pragma unroll
                    for (int jc = 0; jc < 8; jc++) acc[p][jc] = 0ull;

                const float* ob = &osT[rg * 8];
                const float* wb = &wo[cg * 8];
#pragma unroll
                for (int j = 0; j < 32; j++) {
                    float2 a0 = *(const float2*)&ob[j * RP + 0];
                    float2 a1 = *(const float2*)&ob[j * RP + 2];
                    float2 a2 = *(const float2*)&ob[j * RP + 4];
                    float2 a3 = *(const float2*)&ob[j * RP + 6];
                    float4 w0 = *(const float4*)&wb[j * 128];
                    float4 w1 = *(const float4*)&wb[j * 128 + 4];
                    ull ap[4] = { pack2(a0.x, a0.y), pack2(a1.x, a1.y),
                                  pack2(a2.x, a2.y), pack2(a3.x, a3.y) };
                    ull bp[8] = { pack2(w0.x, w0.x), pack2(w0.y, w0.y),
                                  pack2(w0.z, w0.z), pack2(w0.w, w0.w),
                                  pack2(w1.x, w1.x), pack2(w1.y, w1.y),
                                  pack2(w1.z, w1.z), pack2(w1.w, w1.w) };
#pragma unroll
                    for (int p = 0; p < 4; p++)
#pragma unroll
                        for (int jc = 0; jc < 8; jc++)
                            acc[p][jc] = ffma2(ap[p], bp[jc], acc[p][jc]);
                }
#pragma unroll
                for (int jc = 0; jc < 8; jc++) {
                    const int n = cg * 8 + jc;
                    const float bia = bo[n];
#pragma unroll
                    for (int p = 0; p < 4; p++) {
                        float2 v = unpack2(acc[p][jc]);
                        const int r0 = rg * 8 + 2 * p;
                        if (axis == 0) {
                            otT[n * RP + r0]     = v.x + bia;
                            otT[n * RP + r0 + 1] = v.y + bia;
                        } else {
                            float u0 = v.x + bia + otT[n * RP + r0];
                            float u1 = v.y + bia + otT[n * RP + r0 + 1];
                            hsT[n * RP + r0]     = (u0 > 0.f) ? u0 : 0.2f * u0;
                            hsT[n * RP + r0 + 1] = (u1 > 0.f) ? u1 : 0.2f * u1;
                        }
                    }
                }
            }
            __syncthreads();
        }
    }

    // ---- decoder: dot(h_flat, Wd) + bias, sigmoid ----
    float acc = 0.f;
    for (int f = tid; f < 10240; f += 256) {
        int r = f >> 7, d = f & 127;
        acc += hsT[d * RP + r] * Wd[f];
    }
#pragma unroll
    for (int off = 16; off; off >>= 1) acc += __shfl_down_sync(0xffffffffu, acc, off);
    if ((tid & 31) == 0) qs[tid >> 5] = acc;   // reuse qs as scratch
    __syncthreads();
    if (tid == 0) {
        float s = 0.f;
#pragma unroll
        for (int w = 0; w < 8; w++) s += qs[w];
        s += bd[0];
        out[b] = 1.f / (1.f + __expf(-s));
    }
}

// ---------------------------------------------------------------------------
// Launch
// ---------------------------------------------------------------------------
extern "C" void kernel_launch(void* const* d_in, const int* in_sizes, int n_in,
                              void* d_out, int out_size)
{
    const float* x     = (const float*)d_in[0];
    const float* n1    = (const float*)d_in[1];
    const float* n2    = (const float*)d_in[2];
    const float* W_emb = (const float*)d_in[3];
    const float* b_emb = (const float*)d_in[4];
    const float* Wq    = (const float*)d_in[5];
    const float* Wkv   = (const float*)d_in[6];
    const float* Wout  = (const float*)d_in[7];
    const float* bout  = (const float*)d_in[8];
    const float* W_dec = (const float*)d_in[9];
    const float* b_dec = (const float*)d_in[10];
    float* out = (float*)d_out;

    cudaFuncSetAttribute(mega_kernel, cudaFuncAttributeMaxDynamicSharedMemorySize, MEGA_BYTES);

    dim3 eg(M_TOT / BM, KSPLIT);
    emb_kernel<<<eg, 256>>>(x, n1, n2, W_emb);

    mega_kernel<<<B_, 256, MEGA_BYTES>>>(Wq, Wkv, Wout, bout, b_emb, W_dec, b_dec, out);
}

// round 12
// speedup vs baseline: 1.3552x; 1.3552x over previous
#include <cuda_runtime.h>
#include <cuda_bf16.h>
#include <cstdint>

typedef unsigned long long ull;
typedef unsigned int uint;

// ---------------------------------------------------------------------------
// f32x2 packed FMA helpers (mega kernel)
// ---------------------------------------------------------------------------
__device__ __forceinline__ ull ffma2(ull a, ull b, ull c) {
    ull d;
    asm("fma.rn.f32x2 %0, %1, %2, %3;" : "=l"(d) : "l"(a), "l"(b), "l"(c));
    return d;
}
__device__ __forceinline__ ull pack2(float lo, float hi) {
    ull d;
    asm("mov.b64 %0, {%1, %2};" : "=l"(d) : "f"(lo), "f"(hi));
    return d;
}
__device__ __forceinline__ float2 unpack2(ull v) {
    float2 r;
    asm("mov.b64 {%0, %1}, %2;" : "=f"(r.x), "=f"(r.y) : "l"(v));
    return r;
}

// pack 2 fp32 -> bf16x2 (v0 -> lower half, v1 -> upper half)
__device__ __forceinline__ uint pbf(float v0, float v1) {
    uint r;
    asm("cvt.rn.bf16x2.f32 %0, %1, %2;" : "=r"(r) : "f"(v1), "f"(v0));
    return r;
}

// ---------------------------------------------------------------------------
// Problem constants
// ---------------------------------------------------------------------------
#define B_    128
#define T_    20
#define C_    4
#define HW_   4096
#define D_    128

#define M_TOT (B_ * T_ * C_)   // 10240
#define K_TOT HW_              // 4096
#define N_TOT D_               // 128

#define KSPLIT 4
#define KSEG   (K_TOT / KSPLIT)   // 1024
#define KC     32                 // K per chunk
#define NCHUNK (KSEG / KC)        // 32
#define MTILE  128

// scratch (device globals; no allocation allowed)
__device__ float g_part[KSPLIT * M_TOT * N_TOT];
__device__ __align__(16) __nv_bfloat16 g_whiT[N_TOT * K_TOT];  // W^T hi, K-major
__device__ __align__(16) __nv_bfloat16 g_wloT[N_TOT * K_TOT];  // W^T lo, K-major

// ---------------------------------------------------------------------------
// bf16 MMA (m16n8k16, fp32 accumulate) — portable PTX, HMMA on sm_103
// ---------------------------------------------------------------------------
#define MMA_BF16(d, a0, a1, a2, a3, b0, b1)                                   \
    asm volatile(                                                             \
        "mma.sync.aligned.m16n8k16.row.col.f32.bf16.bf16.f32 "                \
        "{%0,%1,%2,%3},{%4,%5,%6,%7},{%8,%9},{%0,%1,%2,%3};"                  \
        : "+f"((d)[0]), "+f"((d)[1]), "+f"((d)[2]), "+f"((d)[3])              \
        : "r"(a0), "r"(a1), "r"(a2), "r"(a3), "r"(b0), "r"(b1))

__device__ __forceinline__ void cp_async16(void* dst_smem, const void* src_gmem) {
    uint ds = (uint)__cvta_generic_to_shared(dst_smem);
    asm volatile("cp.async.cg.shared.global [%0], [%1], 16;"
                 :: "r"(ds), "l"(__cvta_generic_to_global(src_gmem)) : "memory");
}
__device__ __forceinline__ void cp_async_commit_wait0() {
    asm volatile("cp.async.commit_group;\ncp.async.wait_group 0;" ::: "memory");
}

// ---------------------------------------------------------------------------
// Kernel 0: convert + transpose W_emb into K-major bf16 hi/lo
// ---------------------------------------------------------------------------
__global__ void conv_w_kernel(const float* __restrict__ W) {
    int idx = blockIdx.x * 256 + threadIdx.x;
    if (idx >= K_TOT * N_TOT) return;
    int k = idx >> 7, n = idx & 127;
    float w = W[idx];
    __nv_bfloat16 hi = __float2bfloat16(w);
    float hif = __bfloat162float(hi);
    __nv_bfloat16 lo = __float2bfloat16(w - hif);
    g_whiT[(size_t)n * K_TOT + k] = hi;
    g_wloT[(size_t)n * K_TOT + k] = lo;
}

// ---------------------------------------------------------------------------
// Kernel 1: HMMA embedding GEMM (noise-fused, bf16 hi/lo split, K-split x4)
//   grid (80, 4), 256 threads (8 warps, each warp: m16 x n128).
//   smem rows padded to 80B (20 words) => conflict-free fragment LDS.
// ---------------------------------------------------------------------------
#define ROWB 80                     // bytes per padded smem row (32 bf16 + pad)
#define A_BYTES (MTILE * ROWB)      // 10240
#define B_BYTES (N_TOT * ROWB)      // 10240

__global__ __launch_bounds__(256) void emb_mma_kernel(
    const float* __restrict__ X, const float* __restrict__ N1,
    const float* __restrict__ N2)
{
    __shared__ __align__(16) unsigned char sm[4 * A_BYTES];   // 40 KB
    unsigned char* Ahi = sm;
    unsigned char* Alo = sm + A_BYTES;
    unsigned char* Bhi = sm + 2 * A_BYTES;
    unsigned char* Blo = sm + 3 * A_BYTES;

    const int tid  = threadIdx.x;
    const int wid  = tid >> 5;
    const int lane = tid & 31;
    const int quad = lane >> 2;      // 0..7
    const int tq   = lane & 3;       // 0..3
    const int m0   = blockIdx.x * MTILE;
    const int ks0  = blockIdx.y * KSEG;

    // A producer mapping: 1024 float4-tasks/chunk, 4 reps/thread
    // idx = tid + 256*r : row = idx>>3 (0..127), seg = idx&7 (float4 within 32k)
    // B producer mapping: 512 16B-segs per hi/lo, 2 reps/thread
    // idx = tid + 256*r : n = idx>>2, seg = idx&3

    float acc[16][4];
#pragma unroll
    for (int nt = 0; nt < 16; nt++)
#pragma unroll
        for (int j = 0; j < 4; j++) acc[nt][j] = 0.f;

    const int arow = tid >> 3, aseg = tid & 7;
    const int bn = tid >> 2, bseg = tid & 3;

    for (int i = 0; i < NCHUNK; i++) {
        const long kbase = (long)ks0 + i * KC;

        // ---- B: cp.async preconverted bf16 hi/lo ----
#pragma unroll
        for (int r = 0; r < 2; r++) {
            const int n = bn + r * 64;
            const size_t so = ((size_t)n * K_TOT + kbase) * 2 + bseg * 16;
            cp_async16(Bhi + n * ROWB + bseg * 16, (const char*)g_whiT + so);
            cp_async16(Blo + n * ROWB + bseg * 16, (const char*)g_wloT + so);
        }

        // ---- A: LDG fp32, fuse noise, split hi/lo, STS ----
        float4 xs[4], s1[4], s2[4];
#pragma unroll
        for (int r = 0; r < 4; r++) {
            const int row = arow + r * 32;
            const long off = (long)(m0 + row) * K_TOT + kbase + aseg * 4;
            xs[r] = *(const float4*)(X + off);
            s1[r] = *(const float4*)(N1 + off);
            s2[r] = *(const float4*)(N2 + off);
        }
#pragma unroll
        for (int r = 0; r < 4; r++) {
            const int row = arow + r * 32;
            float v0 = xs[r].x + 1e-3f * s1[r].x + 1e-4f * s2[r].x;
            float v1 = xs[r].y + 1e-3f * s1[r].y + 1e-4f * s2[r].y;
            float v2 = xs[r].z + 1e-3f * s1[r].z + 1e-4f * s2[r].z;
            float v3 = xs[r].w + 1e-3f * s1[r].w + 1e-4f * s2[r].w;
            uint h01 = pbf(v0, v1), h23 = pbf(v2, v3);
            float l0 = v0 - __uint_as_float(h01 << 16);
            float l1 = v1 - __uint_as_float(h01 & 0xffff0000u);
            float l2 = v2 - __uint_as_float(h23 << 16);
            float l3 = v3 - __uint_as_float(h23 & 0xffff0000u);
            uint lo01 = pbf(l0, l1), lo23 = pbf(l2, l3);
            *(uint2*)(Ahi + row * ROWB + aseg * 8) = make_uint2(h01, h23);
            *(uint2*)(Alo + row * ROWB + aseg * 8) = make_uint2(lo01, lo23);
        }

        cp_async_commit_wait0();
        __syncthreads();

        // ---- consumer: warp wid computes rows [wid*16, +16), all 128 n ----
        const unsigned char* arow_hi = Ahi + (wid * 16 + quad) * ROWB;
        const unsigned char* arow_lo = Alo + (wid * 16 + quad) * ROWB;
#pragma unroll
        for (int ks = 0; ks < 2; ks++) {
            const int ko = ks * 32 + tq * 4;   // byte offset of this lane's k-pair
            uint ah0 = *(const uint*)(arow_hi + ko);
            uint ah1 = *(const uint*)(arow_hi + 640 + ko);      // +8 rows
            uint ah2 = *(const uint*)(arow_hi + ko + 16);       // k+8
            uint ah3 = *(const uint*)(arow_hi + 640 + ko + 16);
            uint al0 = *(const uint*)(arow_lo + ko);
            uint al1 = *(const uint*)(arow_lo + 640 + ko);
            uint al2 = *(const uint*)(arow_lo + ko + 16);
            uint al3 = *(const uint*)(arow_lo + 640 + ko + 16);
#pragma unroll
            for (int nt = 0; nt < 16; nt++) {
                const int nb = (nt * 8 + quad) * ROWB + ko;
                uint bh0 = *(const uint*)(Bhi + nb);
                uint bh1 = *(const uint*)(Bhi + nb + 16);
                uint bl0 = *(const uint*)(Blo + nb);
                uint bl1 = *(const uint*)(Blo + nb + 16);
                MMA_BF16(acc[nt], ah0, ah1, ah2, ah3, bh0, bh1);
                MMA_BF16(acc[nt], ah0, ah1, ah2, ah3, bl0, bl1);
                MMA_BF16(acc[nt], al0, al1, al2, al3, bh0, bh1);
            }
        }
        __syncthreads();
    }

    // ---- epilogue: write fp32 partials ----
    float* gp = g_part + (size_t)blockIdx.y * (M_TOT * N_TOT);
    const int row0 = m0 + wid * 16 + quad;
#pragma unroll
    for (int nt = 0; nt < 16; nt++) {
        const int col = nt * 8 + tq * 2;
        *(float2*)(gp + (size_t)row0 * N_TOT + col)       = make_float2(acc[nt][0], acc[nt][1]);
        *(float2*)(gp + (size_t)(row0 + 8) * N_TOT + col) = make_float2(acc[nt][2], acc[nt][3]);
    }
}

// ---------------------------------------------------------------------------
// Mega kernel (512 threads): per-batch fused attention blocks + decoder.
// ---------------------------------------------------------------------------
#define RP 82

#define MEGA_FLOATS (128*RP + 128*RP + 128*96 + 32*128 + 128 + 3*80*32 + 32*RP)
#define MEGA_BYTES  (MEGA_FLOATS * 4)

__global__ __launch_bounds__(512) void mega_kernel(
    const float* __restrict__ Wq,   // [2][2][128][32]
    const float* __restrict__ Wkv,  // [2][2][128][64]
    const float* __restrict__ Wout, // [2][2][32][128]
    const float* __restrict__ Bout, // [2][2][128]
    const float* __restrict__ Bemb, // [128]
    const float* __restrict__ Wd,   // [10240]
    const float* __restrict__ bd,   // [1]
    float* __restrict__ out)
{
    extern __shared__ float smf[];
    float* hsT = smf;                   // [128][RP]
    float* otT = hsT + 128 * RP;        // [128][RP]
    float* wp  = otT + 128 * RP;        // [128][96]
    float* wo  = wp  + 128 * 96;        // [32][128]
    float* bo  = wo  + 32 * 128;        // [128]
    float* qs  = bo  + 128;             // [80][32]
    float* ks  = qs  + 80 * 32;
    float* vs  = ks  + 80 * 32;
    float* osT = vs  + 80 * 32;         // [32][RP]

    const int tid = threadIdx.x;
    const int b   = blockIdx.x;

    // ---- combine 4 GEMM partials + bias + leaky, transpose into smem ----
    {
        const size_t bo0 = (size_t)b * (T_ * C_ * D_);
        const float4* p0 = (const float4*)(g_part + bo0);
        const float4* p1 = (const float4*)(g_part + 1 * (size_t)(M_TOT * N_TOT) + bo0);
        const float4* p2 = (const float4*)(g_part + 2 * (size_t)(M_TOT * N_TOT) + bo0);
        const float4* p3 = (const float4*)(g_part + 3 * (size_t)(M_TOT * N_TOT) + bo0);
        for (int v = tid; v < 2560; v += 512) {
            float4 a = p0[v], c = p1[v], d = p2[v], e = p3[v];
            const int r = v >> 5, d0 = (v & 31) * 4;
            float u0 = a.x + c.x + d.x + e.x + Bemb[d0 + 0];
            float u1 = a.y + c.y + d.y + e.y + Bemb[d0 + 1];
            float u2 = a.z + c.z + d.z + e.z + Bemb[d0 + 2];
            float u3 = a.w + c.w + d.w + e.w + Bemb[d0 + 3];
            hsT[(d0 + 0) * RP + r] = (u0 > 0.f) ? u0 : 0.2f * u0;
            hsT[(d0 + 1) * RP + r] = (u1 > 0.f) ? u1 : 0.2f * u1;
            hsT[(d0 + 2) * RP + r] = (u2 > 0.f) ? u2 : 0.2f * u2;
            hsT[(d0 + 3) * RP + r] = (u3 > 0.f) ? u3 : 0.2f * u3;
        }
    }
    __syncthreads();

    for (int blk = 0; blk < 2; blk++) {
        for (int axis = 0; axis < 2; axis++) {
            const int s = blk * 2 + axis;

            // ---- stage weights ----
            const float4* wq4  = (const float4*)(Wq  + s * 128 * 32);
            const float4* wkv4 = (const float4*)(Wkv + s * 128 * 64);
            for (int f = tid; f < 128 * 24; f += 512) {
                int d = f / 24, q4 = f - d * 24;
                float4 v = (q4 < 8) ? wq4[d * 8 + q4] : wkv4[d * 16 + (q4 - 8)];
                *(float4*)&wp[d * 96 + q4 * 4] = v;
            }
            const float4* wo4 = (const float4*)(Wout + s * 32 * 128);
            for (int f = tid; f < 1024; f += 512) ((float4*)wo)[f] = wo4[f];
            if (tid < 128) bo[tid] = Bout[s * 128 + tid];
            __syncthreads();

            // ---- qkv projection: 80 x 96, thread tile 4x4 (480 tasks) ----
            if (tid < 480) {
                const int rg = tid / 24;          // 0..19 (rows rg*4..+3)
                const int cg = tid - rg * 24;     // 0..23 (cols cg*4..+3)
                ull acc[2][4];
#pragma unroll
                for (int p = 0; p < 2; p++)
#pragma unroll
                    for (int j = 0; j < 4; j++) acc[p][j] = 0ull;

                const float* hb = &hsT[rg * 4];
                const float* wb = &wp[cg * 4];
#pragma unroll 4
                for (int d = 0; d < 128; d++) {
                    float2 a0 = *(const float2*)&hb[d * RP + 0];
                    float2 a1 = *(const float2*)&hb[d * RP + 2];
                    float4 w  = *(const float4*)&wb[d * 96];
                    ull ap0 = pack2(a0.x, a0.y), ap1 = pack2(a1.x, a1.y);
                    ull bp0 = pack2(w.x, w.x), bp1 = pack2(w.y, w.y);
                    ull bp2 = pack2(w.z, w.z), bp3 = pack2(w.w, w.w);
                    acc[0][0] = ffma2(ap0, bp0, acc[0][0]);
                    acc[0][1] = ffma2(ap0, bp1, acc[0][1]);
                    acc[0][2] = ffma2(ap0, bp2, acc[0][2]);
                    acc[0][3] = ffma2(ap0, bp3, acc[0][3]);
                    acc[1][0] = ffma2(ap1, bp0, acc[1][0]);
                    acc[1][1] = ffma2(ap1, bp1, acc[1][1]);
                    acc[1][2] = ffma2(ap1, bp2, acc[1][2]);
                    acc[1][3] = ffma2(ap1, bp3, acc[1][3]);
                }
                const int which = cg >> 3;   // 0=q, 1=k, 2=v
                float* dst = (which == 0) ? qs : (which == 1) ? ks : vs;
                const int lj = (cg & 7) * 4;
#pragma unroll
                for (int p = 0; p < 2; p++) {
                    const int r0 = rg * 4 + 2 * p;
#pragma unroll
                    for (int jc = 0; jc < 4; jc++) {
                        float2 v = unpack2(acc[p][jc]);
                        dst[r0 * 32 + lj + jc]       = v.x;
                        dst[(r0 + 1) * 32 + lj + jc] = v.y;
                    }
                }
            }
            __syncthreads();

            // ---- attention core (640 tasks) ----
            for (int o = tid; o < 640; o += 512) {
                if (axis == 0) {
                    const int t  = o % 20;
                    const int ch = o / 20;
                    const int c  = ch & 3, h = ch >> 2;
                    const int r  = t * 4 + c;
                    const float* qp = &qs[r * 32 + h * 4];
                    float p[20];
                    float mx = -1e30f;
#pragma unroll
                    for (int s2 = 0; s2 < 20; s2++) {
                        const float* kp = &ks[(s2 * 4 + c) * 32 + h * 4];
                        float d = (qp[0]*kp[0] + qp[1]*kp[1] + qp[2]*kp[2] + qp[3]*kp[3]) * 0.5f;
                        p[s2] = d;
                        mx = fmaxf(mx, d);
                    }
                    float sum = 0.f;
#pragma unroll
                    for (int s2 = 0; s2 < 20; s2++) { p[s2] = __expf(p[s2] - mx); sum += p[s2]; }
                    float inv = 1.f / sum;
                    float o0 = 0.f, o1 = 0.f, o2 = 0.f, o3 = 0.f;
#pragma unroll
                    for (int s2 = 0; s2 < 20; s2++) {
                        const float* vp = &vs[(s2 * 4 + c) * 32 + h * 4];
                        float w = p[s2] * inv;
                        o0 += w * vp[0]; o1 += w * vp[1]; o2 += w * vp[2]; o3 += w * vp[3];
                    }
                    osT[(h*4 + 0) * RP + r] = o0;
                    osT[(h*4 + 1) * RP + r] = o1;
                    osT[(h*4 + 2) * RP + r] = o2;
                    osT[(h*4 + 3) * RP + r] = o3;
                } else {
                    const int cq = o & 3;
                    const int h  = (o >> 2) & 7;
                    const int t  = o >> 5;
                    const int r  = t * 4 + cq;
                    const float* qp = &qs[r * 32 + h * 4];
                    float p[4];
                    float mx = -1e30f;
#pragma unroll
                    for (int s2 = 0; s2 < 4; s2++) {
                        const float* kp = &ks[(t * 4 + s2) * 32 + h * 4];
                        float d = (qp[0]*kp[0] + qp[1]*kp[1] + qp[2]*kp[2] + qp[3]*kp[3]) * 0.5f;
                        p[s2] = d;
                        mx = fmaxf(mx, d);
                    }
                    float sum = 0.f;
#pragma unroll
                    for (int s2 = 0; s2 < 4; s2++) { p[s2] = __expf(p[s2] - mx); sum += p[s2]; }
                    float inv = 1.f / sum;
                    float o0 = 0.f, o1 = 0.f, o2 = 0.f, o3 = 0.f;
#pragma unroll
                    for (int s2 = 0; s2 < 4; s2++) {
                        const float* vp = &vs[(t * 4 + s2) * 32 + h * 4];
                        float w = p[s2] * inv;
                        o0 += w * vp[0]; o1 += w * vp[1]; o2 += w * vp[2]; o3 += w * vp[3];
                    }
                    osT[(h*4 + 0) * RP + r] = o0;
                    osT[(h*4 + 1) * RP + r] = o1;
                    osT[(h*4 + 2) * RP + r] = o2;
                    osT[(h*4 + 3) * RP + r] = o3;
                }
            }
            __syncthreads();

            // ---- output projection: 80 x 128, thread tile 4x8 (320 tasks) ----
            if (tid < 320) {
                const int rg = tid >> 4;          // 0..19
                const int cg = tid & 15;          // cols cg*8..+7
                ull acc[2][8];
#pragma unroll
                for (int p = 0; p < 2; p++)
#pragma unroll
                    for (int jc = 0; jc < 8; jc++) acc[p][jc] = 0ull;

                const float* ob = &osT[rg * 4];
                const float* wb = &wo[cg * 8];
#pragma unroll
                for (int j = 0; j < 32; j++) {
                    float2 a0 = *(const float2*)&ob[j * RP + 0];
                    float2 a1 = *(const float2*)&ob[j * RP + 2];
                    float4 w0 = *(const float4*)&wb[j * 128];
                    float4 w1 = *(const float4*)&wb[j * 128 + 4];
                    ull ap[2] = { pack2(a0.x, a0.y), pack2(a1.x, a1.y) };
                    ull bp[8] = { pack2(w0.x, w0.x), pack2(w0.y, w0.y),
                                  pack2(w0.z, w0.z), pack2(w0.w, w0.w),
                                  pack2(w1.x, w1.x), pack2(w1.y, w1.y),
                                  pack2(w1.z, w1.z), pack2(w1.w, w1.w) };
#pragma unroll
                    for (int p = 0; p < 2; p++)
#pragma unroll
                        for (int jc = 0; jc < 8; jc++)
                            acc[p][jc] = ffma2(ap[p], bp[jc], acc[p][jc]);
                }
#pragma unroll
                for (int jc = 0; jc < 8; jc++) {
                    const int n = cg * 8 + jc;
                    const float bia = bo[n];
#pragma unroll
                    for (int p = 0; p < 2; p++) {
                        float2 v = unpack2(acc[p][jc]);
                        const int r0 = rg * 4 + 2 * p;
                        if (axis == 0) {
                            otT[n * RP + r0]     = v.x + bia;
                            otT[n * RP + r0 + 1] = v.y + bia;
                        } else {
                            float u0 = v.x + bia + otT[n * RP + r0];
                            float u1 = v.y + bia + otT[n * RP + r0 + 1];
                            hsT[n * RP + r0]     = (u0 > 0.f) ? u0 : 0.2f * u0;
                            hsT[n * RP + r0 + 1] = (u1 > 0.f) ? u1 : 0.2f * u1;
                        }
                    }
                }
            }
            __syncthreads();
        }
    }

    // ---- decoder ----
    float acc = 0.f;
    for (int f = tid; f < 10240; f += 512) {
        int r = f >> 7, d = f & 127;
        acc += hsT[d * RP + r] * Wd[f];
    }
#pragma unroll
    for (int off = 16; off; off >>= 1) acc += __shfl_down_sync(0xffffffffu, acc, off);
    if ((tid & 31) == 0) qs[tid >> 5] = acc;   // reuse qs as scratch (16 warps)
    __syncthreads();
    if (tid == 0) {
        float s = 0.f;
#pragma unroll
        for (int w = 0; w < 16; w++) s += qs[w];
        s += bd[0];
        out[b] = 1.f / (1.f + __expf(-s));
    }
}

// ---------------------------------------------------------------------------
// Launch
// ---------------------------------------------------------------------------
extern "C" void kernel_launch(void* const* d_in, const int* in_sizes, int n_in,
                              void* d_out, int out_size)
{
    const float* x     = (const float*)d_in[0];
    const float* n1    = (const float*)d_in[1];
    const float* n2    = (const float*)d_in[2];
    const float* W_emb = (const float*)d_in[3];
    const float* b_emb = (const float*)d_in[4];
    const float* Wq    = (const float*)d_in[5];
    const float* Wkv   = (const float*)d_in[6];
    const float* Wout  = (const float*)d_in[7];
    const float* bout  = (const float*)d_in[8];
    const float* W_dec = (const float*)d_in[9];
    const float* b_dec = (const float*)d_in[10];
    float* out = (float*)d_out;

    cudaFuncSetAttribute(mega_kernel, cudaFuncAttributeMaxDynamicSharedMemorySize, MEGA_BYTES);

    conv_w_kernel<<<(K_TOT * N_TOT + 255) / 256, 256>>>(W_emb);

    dim3 eg(M_TOT / MTILE, KSPLIT);
    emb_mma_kernel<<<eg, 256>>>(x, n1, n2);

    mega_kernel<<<B_, 512, MEGA_BYTES>>>(Wq, Wkv, Wout, bout, b_emb, W_dec, b_dec, out);
}

// round 13
// speedup vs baseline: 1.6378x; 1.2086x over previous
#include <cuda_runtime.h>
#include <cuda_bf16.h>
#include <cstdint>

typedef unsigned long long ull;
typedef unsigned int uint;

// ---------------------------------------------------------------------------
// f32x2 packed FMA helpers (mega kernel)
// ---------------------------------------------------------------------------
__device__ __forceinline__ ull ffma2(ull a, ull b, ull c) {
    ull d;
    asm("fma.rn.f32x2 %0, %1, %2, %3;" : "=l"(d) : "l"(a), "l"(b), "l"(c));
    return d;
}
__device__ __forceinline__ ull pack2(float lo, float hi) {
    ull d;
    asm("mov.b64 %0, {%1, %2};" : "=l"(d) : "f"(lo), "f"(hi));
    return d;
}
__device__ __forceinline__ float2 unpack2(ull v) {
    float2 r;
    asm("mov.b64 {%0, %1}, %2;" : "=f"(r.x), "=f"(r.y) : "l"(v));
    return r;
}

// pack 2 fp32 -> bf16x2 (v0 -> lower half, v1 -> upper half)
__device__ __forceinline__ uint pbf(float v0, float v1) {
    uint r;
    asm("cvt.rn.bf16x2.f32 %0, %1, %2;" : "=r"(r) : "f"(v1), "f"(v0));
    return r;
}

// ---------------------------------------------------------------------------
// Problem constants
// ---------------------------------------------------------------------------
#define B_    128
#define T_    20
#define C_    4
#define HW_   4096
#define D_    128

#define M_TOT (B_ * T_ * C_)   // 10240
#define K_TOT HW_              // 4096
#define N_TOT D_               // 128

#define KSPLIT 8
#define KSEG   (K_TOT / KSPLIT)   // 512
#define KC     32                 // K per chunk
#define NCHUNK (KSEG / KC)        // 16
#define MTILE  128

// scratch (device globals; no allocation allowed)
__device__ float g_part[KSPLIT * M_TOT * N_TOT];               // 40 MB
__device__ __align__(16) __nv_bfloat16 g_whiT[N_TOT * K_TOT];  // W^T hi, K-major
__device__ __align__(16) __nv_bfloat16 g_wloT[N_TOT * K_TOT];  // W^T lo, K-major

// ---------------------------------------------------------------------------
// bf16 MMA (m16n8k16, fp32 accumulate) — portable PTX, HMMA on sm_103
// ---------------------------------------------------------------------------
#define MMA_BF16(d, a0, a1, a2, a3, b0, b1)                                   \
    asm volatile(                                                             \
        "mma.sync.aligned.m16n8k16.row.col.f32.bf16.bf16.f32 "                \
        "{%0,%1,%2,%3},{%4,%5,%6,%7},{%8,%9},{%0,%1,%2,%3};"                  \
        : "+f"((d)[0]), "+f"((d)[1]), "+f"((d)[2]), "+f"((d)[3])              \
        : "r"(a0), "r"(a1), "r"(a2), "r"(a3), "r"(b0), "r"(b1))

__device__ __forceinline__ void cp_async16(void* dst_smem, const void* src_gmem) {
    uint ds = (uint)__cvta_generic_to_shared(dst_smem);
    asm volatile("cp.async.cg.shared.global [%0], [%1], 16;"
                 :: "r"(ds), "l"(__cvta_generic_to_global(src_gmem)) : "memory");
}
__device__ __forceinline__ void cp_async_commit() {
    asm volatile("cp.async.commit_group;" ::: "memory");
}
__device__ __forceinline__ void cp_async_wait1() {
    asm volatile("cp.async.wait_group 1;" ::: "memory");
}
__device__ __forceinline__ void cp_async_wait0() {
    asm volatile("cp.async.wait_group 0;" ::: "memory");
}

// ---------------------------------------------------------------------------
// Kernel 0: convert + transpose W_emb into K-major bf16 hi/lo (smem-tiled)
//   W: [4096][128] fp32 -> g_w{hi,lo}T: [128][4096] bf16.
//   grid (128, 4), 256 threads, tile 32k x 32n.
// ---------------------------------------------------------------------------
__global__ __launch_bounds__(256) void conv_w_kernel(const float* __restrict__ W) {
    __shared__ float ts[32][33];
    const int tid = threadIdx.x;
    const int j = tid & 31, i0 = tid >> 5;       // j: inner, i0: 0..7
    const int k0 = blockIdx.x * 32, n0 = blockIdx.y * 32;

#pragma unroll
    for (int r = 0; r < 4; r++) {
        const int i = i0 + r * 8;                 // k-local
        ts[i][j] = W[(size_t)(k0 + i) * N_TOT + n0 + j];   // coalesced over n
    }
    __syncthreads();

#pragma unroll
    for (int r = 0; r < 4; r++) {
        const int n = i0 + r * 8;                 // n-local (output row)
        const float w = ts[j][n];                 // k-local = j
        __nv_bfloat16 hi = __float2bfloat16(w);
        float hif = __bfloat162float(hi);
        __nv_bfloat16 lo = __float2bfloat16(w - hif);
        const size_t o = (size_t)(n0 + n) * K_TOT + k0 + j;  // coalesced over k
        g_whiT[o] = hi;
        g_wloT[o] = lo;
    }
}

// ---------------------------------------------------------------------------
// Kernel 1: HMMA embedding GEMM (noise-fused, bf16 hi/lo split, K-split x8)
//   grid (80, 8), 256 threads (8 warps, each warp: m16 x n128), occ 2/SM.
//   smem (dynamic, 60KB): Ahi, Alo single-buffered; Bhi/Blo double-buffered,
//   filled by cp.async one chunk ahead. Rows padded to 80B.
// ---------------------------------------------------------------------------
#define ROWB 80                     // bytes per padded smem row (32 bf16 + pad)
#define TILE_B (MTILE * ROWB)       // 10240
#define OFF_AHI 0
#define OFF_ALO TILE_B
#define OFF_B(buf) (2 * TILE_B + (buf) * 2 * TILE_B)    // {hi, +TILE_B lo}
#define EMB_SMEM (6 * TILE_B)       // 61440

__global__ __launch_bounds__(256, 2) void emb_mma_kernel(
    const float* __restrict__ X, const float* __restrict__ N1,
    const float* __restrict__ N2)
{
    extern __shared__ unsigned char sm[];
    unsigned char* Ahi = sm + OFF_AHI;
    unsigned char* Alo = sm + OFF_ALO;

    const int tid  = threadIdx.x;
    const int wid  = tid >> 5;
    const int lane = tid & 31;
    const int quad = lane >> 2;      // 0..7
    const int tq   = lane & 3;       // 0..3
    const int m0   = blockIdx.x * MTILE;
    const int ks0  = blockIdx.y * KSEG;

    float acc[16][4];
#pragma unroll
    for (int nt = 0; nt < 16; nt++)
#pragma unroll
        for (int j = 0; j < 4; j++) acc[nt][j] = 0.f;

    const int arow = tid >> 3, aseg = tid & 7;   // A: 4 reps of (row+32r)
    const int bn = tid >> 2, bseg = tid & 3;     // B: 2 reps of (n+64r)

    // prologue: B chunk 0 -> buf 0
    {
        const long kbase = ks0;
#pragma unroll
        for (int r = 0; r < 2; r++) {
            const int n = bn + r * 64;
            const size_t so = ((size_t)n * K_TOT + kbase) * 2 + bseg * 16;
            cp_async16(sm + OFF_B(0) + n * ROWB + bseg * 16, (const char*)g_whiT + so);
            cp_async16(sm + OFF_B(0) + TILE_B + n * ROWB + bseg * 16, (const char*)g_wloT + so);
        }
        cp_async_commit();
    }

    for (int i = 0; i < NCHUNK; i++) {
        const int buf = i & 1;
        const long kbase = (long)ks0 + i * KC;

        // ---- prefetch B chunk i+1 into other buffer ----
        if (i + 1 < NCHUNK) {
            const long kn = kbase + KC;
#pragma unroll
            for (int r = 0; r < 2; r++) {
                const int n = bn + r * 64;
                const size_t so = ((size_t)n * K_TOT + kn) * 2 + bseg * 16;
                cp_async16(sm + OFF_B(buf ^ 1) + n * ROWB + bseg * 16,
                           (const char*)g_whiT + so);
                cp_async16(sm + OFF_B(buf ^ 1) + TILE_B + n * ROWB + bseg * 16,
                           (const char*)g_wloT + so);
            }
            cp_async_commit();
        }

        // ---- A: LDG fp32, fuse noise, split hi/lo, STS (2 reps at a time) ----
#pragma unroll
        for (int half = 0; half < 2; half++) {
            float4 xs[2], s1[2], s2[2];
#pragma unroll
            for (int r = 0; r < 2; r++) {
                const int row = arow + (half * 2 + r) * 32;
                const long off = (long)(m0 + row) * K_TOT + kbase + aseg * 4;
                xs[r] = *(const float4*)(X + off);
                s1[r] = *(const float4*)(N1 + off);
                s2[r] = *(const float4*)(N2 + off);
            }
#pragma unroll
            for (int r = 0; r < 2; r++) {
                const int row = arow + (half * 2 + r) * 32;
                float v0 = xs[r].x + 1e-3f * s1[r].x + 1e-4f * s2[r].x;
                float v1 = xs[r].y + 1e-3f * s1[r].y + 1e-4f * s2[r].y;
                float v2 = xs[r].z + 1e-3f * s1[r].z + 1e-4f * s2[r].z;
                float v3 = xs[r].w + 1e-3f * s1[r].w + 1e-4f * s2[r].w;
                uint h01 = pbf(v0, v1), h23 = pbf(v2, v3);
                float l0 = v0 - __uint_as_float(h01 << 16);
                float l1 = v1 - __uint_as_float(h01 & 0xffff0000u);
                float l2 = v2 - __uint_as_float(h23 << 16);
                float l3 = v3 - __uint_as_float(h23 & 0xffff0000u);
                uint lo01 = pbf(l0, l1), lo23 = pbf(l2, l3);
                *(uint2*)(Ahi + row * ROWB + aseg * 8) = make_uint2(h01, h23);
                *(uint2*)(Alo + row * ROWB + aseg * 8) = make_uint2(lo01, lo23);
            }
        }

        // B(i) must have landed; allow B(i+1) to remain in flight
        if (i + 1 < NCHUNK) cp_async_wait1(); else cp_async_wait0();
        __syncthreads();

        // ---- consumer: warp wid computes rows [wid*16, +16), all 128 n ----
        const unsigned char* Bhi = sm + OFF_B(buf);
        const unsigned char* Blo = Bhi + TILE_B;
        const unsigned char* arow_hi = Ahi + (wid * 16 + quad) * ROWB;
        const unsigned char* arow_lo = Alo + (wid * 16 + quad) * ROWB;
#pragma unroll
        for (int ks = 0; ks < 2; ks++) {
            const int ko = ks * 32 + tq * 4;   // byte offset of this lane's k-pair
            uint ah0 = *(const uint*)(arow_hi + ko);
            uint ah1 = *(const uint*)(arow_hi + 640 + ko);      // +8 rows
            uint ah2 = *(const uint*)(arow_hi + ko + 16);       // k+8
            uint ah3 = *(const uint*)(arow_hi + 640 + ko + 16);
            uint al0 = *(const uint*)(arow_lo + ko);
            uint al1 = *(const uint*)(arow_lo + 640 + ko);
            uint al2 = *(const uint*)(arow_lo + ko + 16);
            uint al3 = *(const uint*)(arow_lo + 640 + ko + 16);
#pragma unroll
            for (int nt = 0; nt < 16; nt++) {
                const int nb = (nt * 8 + quad) * ROWB + ko;
                uint bh0 = *(const uint*)(Bhi + nb);
                uint bh1 = *(const uint*)(Bhi + nb + 16);
                uint bl0 = *(const uint*)(Blo + nb);
                uint bl1 = *(const uint*)(Blo + nb + 16);
                MMA_BF16(acc[nt], ah0, ah1, ah2, ah3, bh0, bh1);
                MMA_BF16(acc[nt], ah0, ah1, ah2, ah3, bl0, bl1);
                MMA_BF16(acc[nt], al0, al1, al2, al3, bh0, bh1);
            }
        }
        __syncthreads();
    }

    // ---- epilogue: write fp32 partials ----
    float* gp = g_part + (size_t)blockIdx.y * (M_TOT * N_TOT);
    const int row0 = m0 + wid * 16 + quad;
#pragma unroll
    for (int nt = 0; nt < 16; nt++) {
        const int col = nt * 8 + tq * 2;
        *(float2*)(gp + (size_t)row0 * N_TOT + col)       = make_float2(acc[nt][0], acc[nt][1]);
        *(float2*)(gp + (size_t)(row0 + 8) * N_TOT + col) = make_float2(acc[nt][2], acc[nt][3]);
    }
}

// ---------------------------------------------------------------------------
// Mega kernel (512 threads): per-batch fused attention blocks + decoder.
// ---------------------------------------------------------------------------
#define RP 82

#define MEGA_FLOATS (128*RP + 128*RP + 128*96 + 32*128 + 128 + 3*80*32 + 32*RP)
#define MEGA_BYTES  (MEGA_FLOATS * 4)

__global__ __launch_bounds__(512) void mega_kernel(
    const float* __restrict__ Wq,   // [2][2][128][32]
    const float* __restrict__ Wkv,  // [2][2][128][64]
    const float* __restrict__ Wout, // [2][2][32][128]
    const float* __restrict__ Bout, // [2][2][128]
    const float* __restrict__ Bemb, // [128]
    const float* __restrict__ Wd,   // [10240]
    const float* __restrict__ bd,   // [1]
    float* __restrict__ out)
{
    extern __shared__ float smf[];
    float* hsT = smf;                   // [128][RP]
    float* otT = hsT + 128 * RP;        // [128][RP]
    float* wp  = otT + 128 * RP;        // [128][96]
    float* wo  = wp  + 128 * 96;        // [32][128]
    float* bo  = wo  + 32 * 128;        // [128]
    float* qs  = bo  + 128;             // [80][32]
    float* ks  = qs  + 80 * 32;
    float* vs  = ks  + 80 * 32;
    float* osT = vs  + 80 * 32;         // [32][RP]

    const int tid = threadIdx.x;
    const int b   = blockIdx.x;

    // ---- combine 8 GEMM partials + bias + leaky, transpose into smem ----
    {
        const size_t bo0 = (size_t)b * (T_ * C_ * D_);
        for (int v = tid; v < 2560; v += 512) {
            float4 s = make_float4(0.f, 0.f, 0.f, 0.f);
#pragma unroll
            for (int sp = 0; sp < KSPLIT; sp++) {
                float4 a = *(const float4*)(g_part + (size_t)sp * (M_TOT * N_TOT) + bo0 + v * 4);
                s.x += a.x; s.y += a.y; s.z += a.z; s.w += a.w;
            }
            const int r = v >> 5, d0 = (v & 31) * 4;
            float u0 = s.x + Bemb[d0 + 0];
            float u1 = s.y + Bemb[d0 + 1];
            float u2 = s.z + Bemb[d0 + 2];
            float u3 = s.w + Bemb[d0 + 3];
            hsT[(d0 + 0) * RP + r] = (u0 > 0.f) ? u0 : 0.2f * u0;
            hsT[(d0 + 1) * RP + r] = (u1 > 0.f) ? u1 : 0.2f * u1;
            hsT[(d0 + 2) * RP + r] = (u2 > 0.f) ? u2 : 0.2f * u2;
            hsT[(d0 + 3) * RP + r] = (u3 > 0.f) ? u3 : 0.2f * u3;
        }
    }
    __syncthreads();

    for (int blk = 0; blk < 2; blk++) {
        for (int axis = 0; axis < 2; axis++) {
            const int s = blk * 2 + axis;

            // ---- stage weights ----
            const float4* wq4  = (const float4*)(Wq  + s * 128 * 32);
            const float4* wkv4 = (const float4*)(Wkv + s * 128 * 64);
            for (int f = tid; f < 128 * 24; f += 512) {
                int d = f / 24, q4 = f - d * 24;
                float4 v = (q4 < 8) ? wq4[d * 8 + q4] : wkv4[d * 16 + (q4 - 8)];
                *(float4*)&wp[d * 96 + q4 * 4] = v;
            }
            const float4* wo4 = (const float4*)(Wout + s * 32 * 128);
            for (int f = tid; f < 1024; f += 512) ((float4*)wo)[f] = wo4[f];
            if (tid < 128) bo[tid] = Bout[s * 128 + tid];
            __syncthreads();

            // ---- qkv projection: 80 x 96, thread tile 4x4 (480 tasks) ----
            if (tid < 480) {
                const int rg = tid / 24;          // 0..19 (rows rg*4..+3)
                const int cg = tid - rg * 24;     // 0..23 (cols cg*4..+3)
                ull acc[2][4];
#pragma unroll
                for (int p = 0; p < 2; p++)
#pragma unroll
                    for (int j = 0; j < 4; j++) acc[p][j] = 0ull;

                const float* hb = &hsT[rg * 4];
                const float* wb = &wp[cg * 4];
#pragma unroll 4
                for (int d = 0; d < 128; d++) {
                    float2 a0 = *(const float2*)&hb[d * RP + 0];
                    float2 a1 = *(const float2*)&hb[d * RP + 2];
                    float4 w  = *(const float4*)&wb[d * 96];
                    ull ap0 = pack2(a0.x, a0.y), ap1 = pack2(a1.x, a1.y);
                    ull bp0 = pack2(w.x, w.x), bp1 = pack2(w.y, w.y);
                    ull bp2 = pack2(w.z, w.z), bp3 = pack2(w.w, w.w);
                    acc[0][0] = ffma2(ap0, bp0, acc[0][0]);
                    acc[0][1] = ffma2(ap0, bp1, acc[0][1]);
                    acc[0][2] = ffma2(ap0, bp2, acc[0][2]);
                    acc[0][3] = ffma2(ap0, bp3, acc[0][3]);
                    acc[1][0] = ffma2(ap1, bp0, acc[1][0]);
                    acc[1][1] = ffma2(ap1, bp1, acc[1][1]);
                    acc[1][2] = ffma2(ap1, bp2, acc[1][2]);
                    acc[1][3] = ffma2(ap1, bp3, acc[1][3]);
                }
                const int which = cg >> 3;   // 0=q, 1=k, 2=v
                float* dst = (which == 0) ? qs : (which == 1) ? ks : vs;
                const int lj = (cg & 7) * 4;
#pragma unroll
                for (int p = 0; p < 2; p++) {
                    const int r0 = rg * 4 + 2 * p;
#pragma unroll
                    for (int jc = 0; jc < 4; jc++) {
                        float2 v = unpack2(acc[p][jc]);
                        dst[r0 * 32 + lj + jc]       = v.x;
                        dst[(r0 + 1) * 32 + lj + jc] = v.y;
                    }
                }
            }
            __syncthreads();

            // ---- attention core (640 tasks) ----
            for (int o = tid; o < 640; o += 512) {
                if (axis == 0) {
                    const int t  = o % 20;
                    const int ch = o / 20;
                    const int c  = ch & 3, h = ch >> 2;
                    const int r  = t * 4 + c;
                    const float* qp = &qs[r * 32 + h * 4];
                    float p[20];
                    float mx = -1e30f;
#pragma unroll
                    for (int s2 = 0; s2 < 20; s2++) {
                        const float* kp = &ks[(s2 * 4 + c) * 32 + h * 4];
                        float d = (qp[0]*kp[0] + qp[1]*kp[1] + qp[2]*kp[2] + qp[3]*kp[3]) * 0.5f;
                        p[s2] = d;
                        mx = fmaxf(mx, d);
                    }
                    float sum = 0.f;
#pragma unroll
                    for (int s2 = 0; s2 < 20; s2++) { p[s2] = __expf(p[s2] - mx); sum += p[s2]; }
                    float inv = 1.f / sum;
                    float o0 = 0.f, o1 = 0.f, o2 = 0.f, o3 = 0.f;
#pragma unroll
                    for (int s2 = 0; s2 < 20; s2++) {
                        const float* vp = &vs[(s2 * 4 + c) * 32 + h * 4];
                        float w = p[s2] * inv;
                        o0 += w * vp[0]; o1 += w * vp[1]; o2 += w * vp[2]; o3 += w * vp[3];
                    }
                    osT[(h*4 + 0) * RP + r] = o0;
                    osT[(h*4 + 1) * RP + r] = o1;
                    osT[(h*4 + 2) * RP + r] = o2;
                    osT[(h*4 + 3) * RP + r] = o3;
                } else {
                    const int cq = o & 3;
                    const int h  = (o >> 2) & 7;
                    const int t  = o >> 5;
                    const int r  = t * 4 + cq;
                    const float* qp = &qs[r * 32 + h * 4];
                    float p[4];
                    float mx = -1e30f;
#pragma unroll
                    for (int s2 = 0; s2 < 4; s2++) {
                        const float* kp = &ks[(t * 4 + s2) * 32 + h * 4];
                        float d = (qp[0]*kp[0] + qp[1]*kp[1] + qp[2]*kp[2] + qp[3]*kp[3]) * 0.5f;
                        p[s2] = d;
                        mx = fmaxf(mx, d);
                    }
                    float sum = 0.f;
#pragma unroll
                    for (int s2 = 0; s2 < 4; s2++) { p[s2] = __expf(p[s2] - mx); sum += p[s2]; }
                    float inv = 1.f / sum;
                    float o0 = 0.f, o1 = 0.f, o2 = 0.f, o3 = 0.f;
#pragma unroll
                    for (int s2 = 0; s2 < 4; s2++) {
                        const float* vp = &vs[(t * 4 + s2) * 32 + h * 4];
                        float w = p[s2] * inv;
                        o0 += w * vp[0]; o1 += w * vp[1]; o2 += w * vp[2]; o3 += w * vp[3];
                    }
                    osT[(h*4 + 0) * RP + r] = o0;
                    osT[(h*4 + 1) * RP + r] = o1;
                    osT[(h*4 + 2) * RP + r] = o2;
                    osT[(h*4 + 3) * RP + r] = o3;
                }
            }
            __syncthreads();

            // ---- output projection: 80 x 128, thread tile 4x8 (320 tasks) ----
            if (tid < 320) {
                const int rg = tid >> 4;          // 0..19
                const int cg = tid & 15;          // cols cg*8..+7
                ull acc[2][8];
#pragma unroll
                for (int p = 0; p < 2; p++)
#pragma unroll
                    for (int jc = 0; jc < 8; jc++) acc[p][jc] = 0ull;

                const float* ob = &osT[rg * 4];
                const float* wb = &wo[cg * 8];
#pragma unroll
                for (int j = 0; j < 32; j++) {
                    float2 a0 = *(const float2*)&ob[j * RP + 0];
                    float2 a1 = *(const float2*)&ob[j * RP + 2];
                    float4 w0 = *(const float4*)&wb[j * 128];
                    float4 w1 = *(const float4*)&wb[j * 128 + 4];
                    ull ap[2] = { pack2(a0.x, a0.y), pack2(a1.x, a1.y) };
                    ull bp[8] = { pack2(w0.x, w0.x), pack2(w0.y, w0.y),
                                  pack2(w0.z, w0.z), pack2(w0.w, w0.w),
                                  pack2(w1.x, w1.x), pack2(w1.y, w1.y),
                                  pack2(w1.z, w1.z), pack2(w1.w, w1.w) };
#pragma unroll
                    for (int p = 0; p < 2; p++)
#pragma unroll
                        for (int jc = 0; jc < 8; jc++)
                            acc[p][jc] = ffma2(ap[p], bp[jc], acc[p][jc]);
                }
#pragma unroll
                for (int jc = 0; jc < 8; jc++) {
                    const int n = cg * 8 + jc;
                    const float bia = bo[n];
#pragma unroll
                    for (int p = 0; p < 2; p++) {
                        float2 v = unpack2(acc[p][jc]);
                        const int r0 = rg * 4 + 2 * p;
                        if (axis == 0) {
                            otT[n * RP + r0]     = v.x + bia;
                            otT[n * RP + r0 + 1] = v.y + bia;
                        } else {
                            float u0 = v.x + bia + otT[n * RP + r0];
                            float u1 = v.y + bia + otT[n * RP + r0 + 1];
                            hsT[n * RP + r0]     = (u0 > 0.f) ? u0 : 0.2f * u0;
                            hsT[n * RP + r0 + 1] = (u1 > 0.f) ? u1 : 0.2f * u1;
                        }
                    }
                }
            }
            __syncthreads();
        }
    }

    // ---- decoder ----
    float acc = 0.f;
    for (int f = tid; f < 10240; f += 512) {
        int r = f >> 7, d = f & 127;
        acc += hsT[d * RP + r] * Wd[f];
    }
#pragma unroll
    for (int off = 16; off; off >>= 1) acc += __shfl_down_sync(0xffffffffu, acc, off);
    if ((tid & 31) == 0) qs[tid >> 5] = acc;   // reuse qs as scratch (16 warps)
    __syncthreads();
    if (tid == 0) {
        float s = 0.f;
#pragma unroll
        for (int w = 0; w < 16; w++) s += qs[w];
        s += bd[0];
        out[b] = 1.f / (1.f + __expf(-s));
    }
}

// ---------------------------------------------------------------------------
// Launch
// ---------------------------------------------------------------------------
extern "C" void kernel_launch(void* const* d_in, const int* in_sizes, int n_in,
                              void* d_out, int out_size)
{
    const float* x     = (const float*)d_in[0];
    const float* n1    = (const float*)d_in[1];
    const float* n2    = (const float*)d_in[2];
    const float* W_emb = (const float*)d_in[3];
    const float* b_emb = (const float*)d_in[4];
    const float* Wq    = (const float*)d_in[5];
    const float* Wkv   = (const float*)d_in[6];
    const float* Wout  = (const float*)d_in[7];
    const float* bout  = (const float*)d_in[8];
    const float* W_dec = (const float*)d_in[9];
    const float* b_dec = (const float*)d_in[10];
    float* out = (float*)d_out;

    cudaFuncSetAttribute(emb_mma_kernel, cudaFuncAttributeMaxDynamicSharedMemorySize, EMB_SMEM);
    cudaFuncSetAttribute(mega_kernel, cudaFuncAttributeMaxDynamicSharedMemorySize, MEGA_BYTES);

    dim3 cg(K_TOT / 32, N_TOT / 32);
    conv_w_kernel<<<cg, 256>>>(W_emb);

    dim3 eg(M_TOT / MTILE, KSPLIT);
    emb_mma_kernel<<<eg, 256, EMB_SMEM>>>(x, n1, n2);

    mega_kernel<<<B_, 512, MEGA_BYTES>>>(Wq, Wkv, Wout, bout, b_emb, W_dec, b_dec, out);
}

// round 14
// speedup vs baseline: 1.6905x; 1.0322x over previous
#include <cuda_runtime.h>
#include <cuda_bf16.h>
#include <cstdint>

typedef unsigned long long ull;
typedef unsigned int uint;

// ---------------------------------------------------------------------------
// f32x2 packed FMA helpers (mega kernel)
// ---------------------------------------------------------------------------
__device__ __forceinline__ ull ffma2(ull a, ull b, ull c) {
    ull d;
    asm("fma.rn.f32x2 %0, %1, %2, %3;" : "=l"(d) : "l"(a), "l"(b), "l"(c));
    return d;
}
__device__ __forceinline__ ull pack2(float lo, float hi) {
    ull d;
    asm("mov.b64 %0, {%1, %2};" : "=l"(d) : "f"(lo), "f"(hi));
    return d;
}
__device__ __forceinline__ float2 unpack2(ull v) {
    float2 r;
    asm("mov.b64 {%0, %1}, %2;" : "=f"(r.x), "=f"(r.y) : "l"(v));
    return r;
}

// pack 2 fp32 -> bf16x2 (v0 -> lower half, v1 -> upper half)
__device__ __forceinline__ uint pbf(float v0, float v1) {
    uint r;
    asm("cvt.rn.bf16x2.f32 %0, %1, %2;" : "=r"(r) : "f"(v1), "f"(v0));
    return r;
}

// ---------------------------------------------------------------------------
// Problem constants
// ---------------------------------------------------------------------------
#define B_    128
#define T_    20
#define C_    4
#define HW_   4096
#define D_    128

#define M_TOT (B_ * T_ * C_)   // 10240
#define K_TOT HW_              // 4096
#define N_TOT D_               // 128

#define KSPLIT 8
#define KSEG   (K_TOT / KSPLIT)   // 512
#define MTILE  128

#define KC     16                 // K per chunk
#define NCHUNK (KSEG / KC)        // 32

// scratch (device globals; no allocation allowed)
__device__ float g_part[KSPLIT * M_TOT * N_TOT];               // 40 MB
__device__ __align__(16) __nv_bfloat16 g_whiT[N_TOT * K_TOT];  // W^T hi, K-major
__device__ __align__(16) __nv_bfloat16 g_wloT[N_TOT * K_TOT];  // W^T lo, K-major

// ---------------------------------------------------------------------------
// bf16 MMA (m16n8k16, fp32 accumulate) — portable PTX, HMMA on sm_103
// ---------------------------------------------------------------------------
#define MMA_BF16(d, a0, a1, a2, a3, b0, b1)                                   \
    asm volatile(                                                             \
        "mma.sync.aligned.m16n8k16.row.col.f32.bf16.bf16.f32 "                \
        "{%0,%1,%2,%3},{%4,%5,%6,%7},{%8,%9},{%0,%1,%2,%3};"                  \
        : "+f"((d)[0]), "+f"((d)[1]), "+f"((d)[2]), "+f"((d)[3])              \
        : "r"(a0), "r"(a1), "r"(a2), "r"(a3), "r"(b0), "r"(b1))

__device__ __forceinline__ void cp_async16(void* dst_smem, const void* src_gmem) {
    uint ds = (uint)__cvta_generic_to_shared(dst_smem);
    asm volatile("cp.async.cg.shared.global [%0], [%1], 16;"
                 :: "r"(ds), "l"(__cvta_generic_to_global(src_gmem)) : "memory");
}
__device__ __forceinline__ void cp_async_commit() {
    asm volatile("cp.async.commit_group;" ::: "memory");
}
__device__ __forceinline__ void cp_async_wait1() {
    asm volatile("cp.async.wait_group 1;" ::: "memory");
}
__device__ __forceinline__ void cp_async_wait0() {
    asm volatile("cp.async.wait_group 0;" ::: "memory");
}

// ---------------------------------------------------------------------------
// Kernel 0: convert + transpose W_emb into K-major bf16 hi/lo (smem-tiled)
// ---------------------------------------------------------------------------
__global__ __launch_bounds__(256) void conv_w_kernel(const float* __restrict__ W) {
    __shared__ float ts[32][33];
    const int tid = threadIdx.x;
    const int j = tid & 31, i0 = tid >> 5;
    const int k0 = blockIdx.x * 32, n0 = blockIdx.y * 32;

#pragma unroll
    for (int r = 0; r < 4; r++) {
        const int i = i0 + r * 8;
        ts[i][j] = W[(size_t)(k0 + i) * N_TOT + n0 + j];
    }
    __syncthreads();

#pragma unroll
    for (int r = 0; r < 4; r++) {
        const int n = i0 + r * 8;
        const float w = ts[j][n];
        __nv_bfloat16 hi = __float2bfloat16(w);
        float hif = __bfloat162float(hi);
        __nv_bfloat16 lo = __float2bfloat16(w - hif);
        const size_t o = (size_t)(n0 + n) * K_TOT + k0 + j;
        g_whiT[o] = hi;
        g_wloT[o] = lo;
    }
}

// ---------------------------------------------------------------------------
// Kernel 1: HMMA embedding GEMM, fully async.
//   grid (80, 8), 256 threads (8 warps, each warp: m16 x n128), occ 2/SM.
//   X/N1/N2 staged raw fp32 via cp.async (double buffered, KC=16); A-fragments
//   built in the consumer (LDS.64 + noise-fuse + bf16 hi/lo split in regs).
//   B bf16 hi/lo staged via cp.async (double buffered).
//   A rows padded to 96B (conflict-free LDS.64), B rows to 48B (conflict-free).
// ---------------------------------------------------------------------------
#define A_PITCH 96
#define A_BUF_B (MTILE * A_PITCH)   // 12288
#define B_PITCH 48
#define B_BUF_B (N_TOT * B_PITCH)   // 6144
#define OFF_BST (6 * A_BUF_B)       // after 2 bufs x 3 arrays of A
#define EMB_SMEM (6 * A_BUF_B + 4 * B_BUF_B)   // 98304 = 96 KB

__global__ __launch_bounds__(256, 2) void emb_mma_kernel(
    const float* __restrict__ X, const float* __restrict__ N1,
    const float* __restrict__ N2)
{
    extern __shared__ unsigned char sm[];

    const int tid  = threadIdx.x;
    const int wid  = tid >> 5;
    const int lane = tid & 31;
    const int quad = lane >> 2;      // 0..7
    const int tq   = lane & 3;       // 0..3
    const int m0   = blockIdx.x * MTILE;
    const int ks0  = blockIdx.y * KSEG;

    float acc[16][4];
#pragma unroll
    for (int nt = 0; nt < 16; nt++)
#pragma unroll
        for (int j = 0; j < 4; j++) acc[nt][j] = 0.f;

    // ---- producer: cp.async one whole chunk (A fp32 x3 + B bf16 x2) ----
    // A: 1536 16B-chunks (3 arrays x 128 rows x 4 segs) -> 6 per thread
    // B: 512 16B-chunks (2 hi/lo x 128 n x 2 segs)      -> 2 per thread
    auto prefetch = [&](int chunk, int buf) {
        const long kb = (long)ks0 + chunk * KC;
#pragma unroll
        for (int r = 0; r < 6; r++) {
            const int idx = tid + 256 * r;
            const int arr = idx >> 9;          // 0..2
            const int rem = idx & 511;
            const int row = rem >> 2, seg = rem & 3;
            const float* src = (arr == 0) ? X : (arr == 1) ? N1 : N2;
            cp_async16(sm + (size_t)(buf * 3 + arr) * A_BUF_B + row * A_PITCH + seg * 16,
                       src + (long)(m0 + row) * K_TOT + kb + seg * 4);
        }
#pragma unroll
        for (int r = 0; r < 2; r++) {
            const int idx = tid + 256 * r;
            const int hl = idx >> 8;           // 0=hi, 1=lo
            const int rem = idx & 255;
            const int n = rem >> 1, seg = rem & 1;
            const __nv_bfloat16* src = hl ? g_wloT : g_whiT;
            cp_async16(sm + OFF_BST + (size_t)(buf * 2 + hl) * B_BUF_B + n * B_PITCH + seg * 16,
                       (const char*)(src + (size_t)n * K_TOT + kb) + seg * 16);
        }
        cp_async_commit();
    };

    prefetch(0, 0);

    const int wr = wid * 16 + quad;    // this lane's base A row

    for (int i = 0; i < NCHUNK; i++) {
        const int buf = i & 1;
        if (i + 1 < NCHUNK) prefetch(i + 1, buf ^ 1);

        if (i + 1 < NCHUNK) cp_async_wait1(); else cp_async_wait0();
        __syncthreads();

        // ---- build A fragments from staged fp32 (fuse noise, hi/lo split) ----
        const unsigned char* Xs = sm + (size_t)buf * 3 * A_BUF_B;
        uint ah[4], al[4];
#pragma unroll
        for (int s = 0; s < 4; s++) {
            // slots: s0=(wr, 2t) s1=(wr+8, 2t) s2=(wr, 2t+8) s3=(wr+8, 2t+8)
            const int row = wr + (s & 1) * 8;
            const int off = row * A_PITCH + tq * 8 + (s >> 1) * 32;
            float2 xv = *(const float2*)(Xs + off);
            float2 v1 = *(const float2*)(Xs + A_BUF_B + off);
            float2 v2 = *(const float2*)(Xs + 2 * A_BUF_B + off);
            float u0 = xv.x + 1e-3f * v1.x + 1e-4f * v2.x;
            float u1 = xv.y + 1e-3f * v1.y + 1e-4f * v2.y;
            uint h = pbf(u0, u1);
            float l0 = u0 - __uint_as_float(h << 16);
            float l1 = u1 - __uint_as_float(h & 0xffff0000u);
            ah[s] = h;
            al[s] = pbf(l0, l1);
        }

        // ---- MMA over all 16 n-tiles ----
        const unsigned char* Bh = sm + OFF_BST + (size_t)buf * 2 * B_BUF_B;
        const unsigned char* Bl = Bh + B_BUF_B;
#pragma unroll
        for (int nt = 0; nt < 16; nt++) {
            const int nb = (nt * 8 + quad) * B_PITCH + tq * 4;
            uint bh0 = *(const uint*)(Bh + nb);
            uint bh1 = *(const uint*)(Bh + nb + 16);
            uint bl0 = *(const uint*)(Bl + nb);
            uint bl1 = *(const uint*)(Bl + nb + 16);
            MMA_BF16(acc[nt], ah[0], ah[1], ah[2], ah[3], bh0, bh1);
            MMA_BF16(acc[nt], ah[0], ah[1], ah[2], ah[3], bl0, bl1);
            MMA_BF16(acc[nt], al[0], al[1], al[2], al[3], bh0, bh1);
        }
        __syncthreads();   // protect buffers before next prefetch overwrites
    }

    // ---- epilogue: write fp32 partials ----
    float* gp = g_part + (size_t)blockIdx.y * (M_TOT * N_TOT);
    const int row0 = m0 + wid * 16 + quad;
#pragma unroll
    for (int nt = 0; nt < 16; nt++) {
        const int col = nt * 8 + tq * 2;
        *(float2*)(gp + (size_t)row0 * N_TOT + col)       = make_float2(acc[nt][0], acc[nt][1]);
        *(float2*)(gp + (size_t)(row0 + 8) * N_TOT + col) = make_float2(acc[nt][2], acc[nt][3]);
    }
}

// ---------------------------------------------------------------------------
// Mega kernel (512 threads): per-batch fused attention blocks + decoder.
// ---------------------------------------------------------------------------
#define RP 82

#define MEGA_FLOATS (128*RP + 128*RP + 128*96 + 32*128 + 128 + 3*80*32 + 32*RP)
#define MEGA_BYTES  (MEGA_FLOATS * 4)

__global__ __launch_bounds__(512) void mega_kernel(
    const float* __restrict__ Wq,   // [2][2][128][32]
    const float* __restrict__ Wkv,  // [2][2][128][64]
    const float* __restrict__ Wout, // [2][2][32][128]
    const float* __restrict__ Bout, // [2][2][128]
    const float* __restrict__ Bemb, // [128]
    const float* __restrict__ Wd,   // [10240]
    const float* __restrict__ bd,   // [1]
    float* __restrict__ out)
{
    extern __shared__ float smf[];
    float* hsT = smf;                   // [128][RP]
    float* otT = hsT + 128 * RP;        // [128][RP]
    float* wp  = otT + 128 * RP;        // [128][96]
    float* wo  = wp  + 128 * 96;        // [32][128]
    float* bo  = wo  + 32 * 128;        // [128]
    float* qs  = bo  + 128;             // [80][32]
    float* ks  = qs  + 80 * 32;
    float* vs  = ks  + 80 * 32;
    float* osT = vs  + 80 * 32;         // [32][RP]

    const int tid = threadIdx.x;
    const int b   = blockIdx.x;

    // ---- combine 8 GEMM partials + bias + leaky, transpose into smem ----
    {
        const size_t bo0 = (size_t)b * (T_ * C_ * D_);
        for (int v = tid; v < 2560; v += 512) {
            float4 s = make_float4(0.f, 0.f, 0.f, 0.f);
#pragma unroll
            for (int sp = 0; sp < KSPLIT; sp++) {
                float4 a = *(const float4*)(g_part + (size_t)sp * (M_TOT * N_TOT) + bo0 + v * 4);
                s.x += a.x; s.y += a.y; s.z += a.z; s.w += a.w;
            }
            const int r = v >> 5, d0 = (v & 31) * 4;
            float u0 = s.x + Bemb[d0 + 0];
            float u1 = s.y + Bemb[d0 + 1];
            float u2 = s.z + Bemb[d0 + 2];
            float u3 = s.w + Bemb[d0 + 3];
            hsT[(d0 + 0) * RP + r] = (u0 > 0.f) ? u0 : 0.2f * u0;
            hsT[(d0 + 1) * RP + r] = (u1 > 0.f) ? u1 : 0.2f * u1;
            hsT[(d0 + 2) * RP + r] = (u2 > 0.f) ? u2 : 0.2f * u2;
            hsT[(d0 + 3) * RP + r] = (u3 > 0.f) ? u3 : 0.2f * u3;
        }
    }
    __syncthreads();

    for (int blk = 0; blk < 2; blk++) {
        for (int axis = 0; axis < 2; axis++) {
            const int s = blk * 2 + axis;

            // ---- stage weights ----
            const float4* wq4  = (const float4*)(Wq  + s * 128 * 32);
            const float4* wkv4 = (const float4*)(Wkv + s * 128 * 64);
            for (int f = tid; f < 128 * 24; f += 512) {
                int d = f / 24, q4 = f - d * 24;
                float4 v = (q4 < 8) ? wq4[d * 8 + q4] : wkv4[d * 16 + (q4 - 8)];
                *(float4*)&wp[d * 96 + q4 * 4] = v;
            }
            const float4* wo4 = (const float4*)(Wout + s * 32 * 128);
            for (int f = tid; f < 1024; f += 512) ((float4*)wo)[f] = wo4[f];
            if (tid < 128) bo[tid] = Bout[s * 128 + tid];
            __syncthreads();

            // ---- qkv projection: 80 x 96, thread tile 4x4 (480 tasks) ----
            if (tid < 480) {
                const int rg = tid / 24;          // 0..19 (rows rg*4..+3)
                const int cg = tid - rg * 24;     // 0..23 (cols cg*4..+3)
                ull acc[2][4];
#pragma unroll
                for (int p = 0; p < 2; p++)
#pragma unroll
                    for (int j = 0; j < 4; j++) acc[p][j] = 0ull;

                const float* hb = &hsT[rg * 4];
                const float* wb = &wp[cg * 4];
#pragma unroll 4
                for (int d = 0; d < 128; d++) {
                    float2 a0 = *(const float2*)&hb[d * RP + 0];
                    float2 a1 = *(const float2*)&hb[d * RP + 2];
                    float4 w  = *(const float4*)&wb[d * 96];
                    ull ap0 = pack2(a0.x, a0.y), ap1 = pack2(a1.x, a1.y);
                    ull bp0 = pack2(w.x, w.x), bp1 = pack2(w.y, w.y);
                    ull bp2 = pack2(w.z, w.z), bp3 = pack2(w.w, w.w);
                    acc[0][0] = ffma2(ap0, bp0, acc[0][0]);
                    acc[0][1] = ffma2(ap0, bp1, acc[0][1]);
                    acc[0][2] = ffma2(ap0, bp2, acc[0][2]);
                    acc[0][3] = ffma2(ap0, bp3, acc[0][3]);
                    acc[1][0] = ffma2(ap1, bp0, acc[1][0]);
                    acc[1][1] = ffma2(ap1, bp1, acc[1][1]);
                    acc[1][2] = ffma2(ap1, bp2, acc[1][2]);
                    acc[1][3] = ffma2(ap1, bp3, acc[1][3]);
                }
                const int which = cg >> 3;   // 0=q, 1=k, 2=v
                float* dst = (which == 0) ? qs : (which == 1) ? ks : vs;
                const int lj = (cg & 7) * 4;
#pragma unroll
                for (int p = 0; p < 2; p++) {
                    const int r0 = rg * 4 + 2 * p;
#pragma unroll
                    for (int jc = 0; jc < 4; jc++) {
                        float2 v = unpack2(acc[p][jc]);
                        dst[r0 * 32 + lj + jc]       = v.x;
                        dst[(r0 + 1) * 32 + lj + jc] = v.y;
                    }
                }
            }
            __syncthreads();

            // ---- attention core (640 tasks) ----
            for (int o = tid; o < 640; o += 512) {
                if (axis == 0) {
                    const int t  = o % 20;
                    const int ch = o / 20;
                    const int c  = ch & 3, h = ch >> 2;
                    const int r  = t * 4 + c;
                    const float* qp = &qs[r * 32 + h * 4];
                    float p[20];
                    float mx = -1e30f;
#pragma unroll
                    for (int s2 = 0; s2 < 20; s2++) {
                        const float* kp = &ks[(s2 * 4 + c) * 32 + h * 4];
                        float d = (qp[0]*kp[0] + qp[1]*kp[1] + qp[2]*kp[2] + qp[3]*kp[3]) * 0.5f;
                        p[s2] = d;
                        mx = fmaxf(mx, d);
                    }
                    float sum = 0.f;
#pragma unroll
                    for (int s2 = 0; s2 < 20; s2++) { p[s2] = __expf(p[s2] - mx); sum += p[s2]; }
                    float inv = 1.f / sum;
                    float o0 = 0.f, o1 = 0.f, o2 = 0.f, o3 = 0.f;
#pragma unroll
                    for (int s2 = 0; s2 < 20; s2++) {
                        const float* vp = &vs[(s2 * 4 + c) * 32 + h * 4];
                        float w = p[s2] * inv;
                        o0 += w * vp[0]; o1 += w * vp[1]; o2 += w * vp[2]; o3 += w * vp[3];
                    }
                    osT[(h*4 + 0) * RP + r] = o0;
                    osT[(h*4 + 1) * RP + r] = o1;
                    osT[(h*4 + 2) * RP + r] = o2;
                    osT[(h*4 + 3) * RP + r] = o3;
                } else {
                    const int cq = o & 3;
                    const int h  = (o >> 2) & 7;
                    const int t  = o >> 5;
                    const int r  = t * 4 + cq;
                    const float* qp = &qs[r * 32 + h * 4];
                    float p[4];
                    float mx = -1e30f;
#pragma unroll
                    for (int s2 = 0; s2 < 4; s2++) {
                        const float* kp = &ks[(t * 4 + s2) * 32 + h * 4];
                        float d = (qp[0]*kp[0] + qp[1]*kp[1] + qp[2]*kp[2] + qp[3]*kp[3]) * 0.5f;
                        p[s2] = d;
                        mx = fmaxf(mx, d);
                    }
                    float sum = 0.f;
#pragma unroll
                    for (int s2 = 0; s2 < 4; s2++) { p[s2] = __expf(p[s2] - mx); sum += p[s2]; }
                    float inv = 1.f / sum;
                    float o0 = 0.f, o1 = 0.f, o2 = 0.f, o3 = 0.f;
#pragma unroll
                    for (int s2 = 0; s2 < 4; s2++) {
                        const float* vp = &vs[(t * 4 + s2) * 32 + h * 4];
                        float w = p[s2] * inv;
                        o0 += w * vp[0]; o1 += w * vp[1]; o2 += w * vp[2]; o3 += w * vp[3];
                    }
                    osT[(h*4 + 0) * RP + r] = o0;
                    osT[(h*4 + 1) * RP + r] = o1;
                    osT[(h*4 + 2) * RP + r] = o2;
                    osT[(h*4 + 3) * RP + r] = o3;
                }
            }
            __syncthreads();

            // ---- output projection: 80 x 128, thread tile 4x8 (320 tasks) ----
            if (tid < 320) {
                const int rg = tid >> 4;          // 0..19
                const int cg = tid & 15;          // cols cg*8..+7
                ull acc[2][8];
#pragma unroll
                for (int p = 0; p < 2; p++)
#pragma unroll
                    for (int jc = 0; jc < 8; jc++) acc[p][jc] = 0ull;

                const float* ob = &osT[rg * 4];
                const float* wb = &wo[cg * 8];
#pragma unroll
                for (int j = 0; j < 32; j++) {
                    float2 a0 = *(const float2*)&ob[j * RP + 0];
                    float2 a1 = *(const float2*)&ob[j * RP + 2];
                    float4 w0 = *(const float4*)&wb[j * 128];
                    float4 w1 = *(const float4*)&wb[j * 128 + 4];
                    ull ap[2] = { pack2(a0.x, a0.y), pack2(a1.x, a1.y) };
                    ull bp[8] = { pack2(w0.x, w0.x), pack2(w0.y, w0.y),
                                  pack2(w0.z, w0.z), pack2(w0.w, w0.w),
                                  pack2(w1.x, w1.x), pack2(w1.y, w1.y),
                                  pack2(w1.z, w1.z), pack2(w1.w, w1.w) };
#pragma unroll
                    for (int p = 0; p < 2; p++)
#pragma unroll
                        for (int jc = 0; jc < 8; jc++)
                            acc[p][jc] = ffma2(ap[p], bp[jc], acc[p][jc]);
                }
#pragma unroll
                for (int jc = 0; jc < 8; jc++) {
                    const int n = cg * 8 + jc;
                    const float bia = bo[n];
#pragma unroll
                    for (int p = 0; p < 2; p++) {
                        float2 v = unpack2(acc[p][jc]);
                        const int r0 = rg * 4 + 2 * p;
                        if (axis == 0) {
                            otT[n * RP + r0]     = v.x + bia;
                            otT[n * RP + r0 + 1] = v.y + bia;
                        } else {
                            float u0 = v.x + bia + otT[n * RP + r0];
                            float u1 = v.y + bia + otT[n * RP + r0 + 1];
                            hsT[n * RP + r0]     = (u0 > 0.f) ? u0 : 0.2f * u0;
                            hsT[n * RP + r0 + 1] = (u1 > 0.f) ? u1 : 0.2f * u1;
                        }
                    }
                }
            }
            __syncthreads();
        }
    }

    // ---- decoder ----
    float acc = 0.f;
    for (int f = tid; f < 10240; f += 512) {
        int r = f >> 7, d = f & 127;
        acc += hsT[d * RP + r] * Wd[f];
    }
#pragma unroll
    for (int off = 16; off; off >>= 1) acc += __shfl_down_sync(0xffffffffu, acc, off);
    if ((tid & 31) == 0) qs[tid >> 5] = acc;   // reuse qs as scratch (16 warps)
    __syncthreads();
    if (tid == 0) {
        float s = 0.f;
#pragma unroll
        for (int w = 0; w < 16; w++) s += qs[w];
        s += bd[0];
        out[b] = 1.f / (1.f + __expf(-s));
    }
}

// ---------------------------------------------------------------------------
// Launch
// ---------------------------------------------------------------------------
extern "C" void kernel_launch(void* const* d_in, const int* in_sizes, int n_in,
                              void* d_out, int out_size)
{
    const float* x     = (const float*)d_in[0];
    const float* n1    = (const float*)d_in[1];
    const float* n2    = (const float*)d_in[2];
    const float* W_emb = (const float*)d_in[3];
    const float* b_emb = (const float*)d_in[4];
    const float* Wq    = (const float*)d_in[5];
    const float* Wkv   = (const float*)d_in[6];
    const float* Wout  = (const float*)d_in[7];
    const float* bout  = (const float*)d_in[8];
    const float* W_dec = (const float*)d_in[9];
    const float* b_dec = (const float*)d_in[10];
    float* out = (float*)d_out;

    cudaFuncSetAttribute(emb_mma_kernel, cudaFuncAttributeMaxDynamicSharedMemorySize, EMB_SMEM);
    cudaFuncSetAttribute(mega_kernel, cudaFuncAttributeMaxDynamicSharedMemorySize, MEGA_BYTES);

    dim3 cg(K_TOT / 32, N_TOT / 32);
    conv_w_kernel<<<cg, 256>>>(W_emb);

    dim3 eg(M_TOT / MTILE, KSPLIT);
    emb_mma_kernel<<<eg, 256, EMB_SMEM>>>(x, n1, n2);

    mega_kernel<<<B_, 512, MEGA_BYTES>>>(Wq, Wkv, Wout, bout, b_emb, W_dec, b_dec, out);
}

// round 15
// speedup vs baseline: 1.7681x; 1.0459x over previous
#include <cuda_runtime.h>
#include <cuda_bf16.h>
#include <cstdint>

typedef unsigned long long ull;
typedef unsigned int uint;

// ---------------------------------------------------------------------------
// f32x2 packed FMA helpers (mega kernel)
// ---------------------------------------------------------------------------
__device__ __forceinline__ ull ffma2(ull a, ull b, ull c) {
    ull d;
    asm("fma.rn.f32x2 %0, %1, %2, %3;" : "=l"(d) : "l"(a), "l"(b), "l"(c));
    return d;
}
__device__ __forceinline__ ull pack2(float lo, float hi) {
    ull d;
    asm("mov.b64 %0, {%1, %2};" : "=l"(d) : "f"(lo), "f"(hi));
    return d;
}
__device__ __forceinline__ float2 unpack2(ull v) {
    float2 r;
    asm("mov.b64 {%0, %1}, %2;" : "=f"(r.x), "=f"(r.y) : "l"(v));
    return r;
}

// pack 2 fp32 -> bf16x2 (v0 -> lower half, v1 -> upper half)
__device__ __forceinline__ uint pbf(float v0, float v1) {
    uint r;
    asm("cvt.rn.bf16x2.f32 %0, %1, %2;" : "=r"(r) : "f"(v1), "f"(v0));
    return r;
}

// ---------------------------------------------------------------------------
// Problem constants
// ---------------------------------------------------------------------------
#define B_    128
#define T_    20
#define C_    4
#define HW_   4096
#define D_    128

#define M_TOT (B_ * T_ * C_)   // 10240
#define K_TOT HW_              // 4096
#define N_TOT D_               // 128

#define KSPLIT 8
#define KSEG   (K_TOT / KSPLIT)   // 512
#define MTILE  128

#define KC     16                 // K per chunk
#define NCHUNK (KSEG / KC)        // 32

// scratch (device globals; no allocation allowed)
__device__ float g_part[KSPLIT * M_TOT * N_TOT];               // 40 MB
__device__ __align__(16) __nv_bfloat16 g_whiT[N_TOT * K_TOT];  // W^T hi, K-major
__device__ __align__(16) __nv_bfloat16 g_wloT[N_TOT * K_TOT];  // W^T lo, K-major

// ---------------------------------------------------------------------------
// bf16 MMA (m16n8k16, fp32 accumulate) — portable PTX, HMMA on sm_103
// ---------------------------------------------------------------------------
#define MMA_BF16(d, a0, a1, a2, a3, b0, b1)                                   \
    asm volatile(                                                             \
        "mma.sync.aligned.m16n8k16.row.col.f32.bf16.bf16.f32 "                \
        "{%0,%1,%2,%3},{%4,%5,%6,%7},{%8,%9},{%0,%1,%2,%3};"                  \
        : "+f"((d)[0]), "+f"((d)[1]), "+f"((d)[2]), "+f"((d)[3])              \
        : "r"(a0), "r"(a1), "r"(a2), "r"(a3), "r"(b0), "r"(b1))

__device__ __forceinline__ void cp_async16(void* dst_smem, const void* src_gmem) {
    uint ds = (uint)__cvta_generic_to_shared(dst_smem);
    asm volatile("cp.async.cg.shared.global [%0], [%1], 16;"
                 :: "r"(ds), "l"(__cvta_generic_to_global(src_gmem)) : "memory");
}
__device__ __forceinline__ void cp_async_commit() {
    asm volatile("cp.async.commit_group;" ::: "memory");
}
__device__ __forceinline__ void cp_async_wait1() {
    asm volatile("cp.async.wait_group 1;" ::: "memory");
}
__device__ __forceinline__ void cp_async_wait0() {
    asm volatile("cp.async.wait_group 0;" ::: "memory");
}

// ---------------------------------------------------------------------------
// Kernel 0: convert + transpose W_emb into K-major bf16 hi/lo (smem-tiled)
// ---------------------------------------------------------------------------
__global__ __launch_bounds__(256) void conv_w_kernel(const float* __restrict__ W) {
    __shared__ float ts[32][33];
    const int tid = threadIdx.x;
    const int j = tid & 31, i0 = tid >> 5;
    const int k0 = blockIdx.x * 32, n0 = blockIdx.y * 32;

#pragma unroll
    for (int r = 0; r < 4; r++) {
        const int i = i0 + r * 8;
        ts[i][j] = W[(size_t)(k0 + i) * N_TOT + n0 + j];
    }
    __syncthreads();

#pragma unroll
    for (int r = 0; r < 4; r++) {
        const int n = i0 + r * 8;
        const float w = ts[j][n];
        __nv_bfloat16 hi = __float2bfloat16(w);
        float hif = __bfloat162float(hi);
        __nv_bfloat16 lo = __float2bfloat16(w - hif);
        const size_t o = (size_t)(n0 + n) * K_TOT + k0 + j;
        g_whiT[o] = hi;
        g_wloT[o] = lo;
    }
}

// ---------------------------------------------------------------------------
// Kernel 1: HMMA embedding GEMM, fully async, 2-MMA scheme.
//   A = bf16(x + noise) (single), W = bf16 hi/lo (preconverted).
//   grid (80, 8), 256 threads = 8 warps tiled 4m x 2n:
//     warp w: mg = w&3 (rows mg*32..+31, two m16 tiles), ng = w>>2 (n-half).
//   X/N1/N2 staged raw fp32 via cp.async (double buffered, KC=16);
//   A-fragments built in consumer (LDS + noise-fuse + bf16 round).
// ---------------------------------------------------------------------------
#define A_PITCH 96
#define A_BUF_B (MTILE * A_PITCH)   // 12288
#define B_PITCH 48
#define B_BUF_B (N_TOT * B_PITCH)   // 6144
#define OFF_BST (6 * A_BUF_B)       // after 2 bufs x 3 arrays of A
#define EMB_SMEM (6 * A_BUF_B + 4 * B_BUF_B)   // 98304 = 96 KB

__global__ __launch_bounds__(256, 2) void emb_mma_kernel(
    const float* __restrict__ X, const float* __restrict__ N1,
    const float* __restrict__ N2)
{
    extern __shared__ unsigned char sm[];

    const int tid  = threadIdx.x;
    const int wid  = tid >> 5;
    const int lane = tid & 31;
    const int quad = lane >> 2;      // 0..7
    const int tq   = lane & 3;       // 0..3
    const int m0   = blockIdx.x * MTILE;
    const int ks0  = blockIdx.y * KSEG;

    const int mg = wid & 3;          // m-group: rows mg*32 .. +31
    const int ng = wid >> 1 >> 1;    // n-group: cols ng*64 .. +63 (wid>>2)

    float acc[2][8][4];
#pragma unroll
    for (int mi = 0; mi < 2; mi++)
#pragma unroll
        for (int nt = 0; nt < 8; nt++)
#pragma unroll
            for (int j = 0; j < 4; j++) acc[mi][nt][j] = 0.f;

    // ---- producer: cp.async one whole chunk (A fp32 x3 + B bf16 x2) ----
    auto prefetch = [&](int chunk, int buf) {
        const long kb = (long)ks0 + chunk * KC;
#pragma unroll
        for (int r = 0; r < 6; r++) {
            const int idx = tid + 256 * r;
            const int arr = idx >> 9;          // 0..2
            const int rem = idx & 511;
            const int row = rem >> 2, seg = rem & 3;
            const float* src = (arr == 0) ? X : (arr == 1) ? N1 : N2;
            cp_async16(sm + (size_t)(buf * 3 + arr) * A_BUF_B + row * A_PITCH + seg * 16,
                       src + (long)(m0 + row) * K_TOT + kb + seg * 4);
        }
#pragma unroll
        for (int r = 0; r < 2; r++) {
            const int idx = tid + 256 * r;
            const int hl = idx >> 8;           // 0=hi, 1=lo
            const int rem = idx & 255;
            const int n = rem >> 1, seg = rem & 1;
            const __nv_bfloat16* src = hl ? g_wloT : g_whiT;
            cp_async16(sm + OFF_BST + (size_t)(buf * 2 + hl) * B_BUF_B + n * B_PITCH + seg * 16,
                       (const char*)(src + (size_t)n * K_TOT + kb) + seg * 16);
        }
        cp_async_commit();
    };

    prefetch(0, 0);

    for (int i = 0; i < NCHUNK; i++) {
        const int buf = i & 1;
        if (i + 1 < NCHUNK) prefetch(i + 1, buf ^ 1);

        if (i + 1 < NCHUNK) cp_async_wait1(); else cp_async_wait0();
        __syncthreads();

        // ---- build A fragments (fuse noise, round to bf16) ----
        const unsigned char* Xs = sm + (size_t)buf * 3 * A_BUF_B;
        uint ah[2][4];
#pragma unroll
        for (int mi = 0; mi < 2; mi++) {
            const int wrm = mg * 32 + mi * 16 + quad;
#pragma unroll
            for (int s = 0; s < 4; s++) {
                // slots: s0=(wrm, 2t) s1=(wrm+8, 2t) s2=(wrm, 2t+8) s3=(wrm+8, 2t+8)
                const int row = wrm + (s & 1) * 8;
                const int off = row * A_PITCH + tq * 8 + (s >> 1) * 32;
                float2 xv = *(const float2*)(Xs + off);
                float2 v1 = *(const float2*)(Xs + A_BUF_B + off);
                float2 v2 = *(const float2*)(Xs + 2 * A_BUF_B + off);
                float u0 = xv.x + 1e-3f * v1.x + 1e-4f * v2.x;
                float u1 = xv.y + 1e-3f * v1.y + 1e-4f * v2.y;
                ah[mi][s] = pbf(u0, u1);
            }
        }

        // ---- MMA over this warp's 8 n-tiles, 2 m-tiles, W hi+lo ----
        const unsigned char* Bh = sm + OFF_BST + (size_t)buf * 2 * B_BUF_B;
        const unsigned char* Bl = Bh + B_BUF_B;
#pragma unroll
        for (int nt = 0; nt < 8; nt++) {
            const int n = ng * 64 + nt * 8 + quad;
            const int nb = n * B_PITCH + tq * 4;
            uint bh0 = *(const uint*)(Bh + nb);
            uint bh1 = *(const uint*)(Bh + nb + 16);
            uint bl0 = *(const uint*)(Bl + nb);
            uint bl1 = *(const uint*)(Bl + nb + 16);
            MMA_BF16(acc[0][nt], ah[0][0], ah[0][1], ah[0][2], ah[0][3], bh0, bh1);
            MMA_BF16(acc[0][nt], ah[0][0], ah[0][1], ah[0][2], ah[0][3], bl0, bl1);
            MMA_BF16(acc[1][nt], ah[1][0], ah[1][1], ah[1][2], ah[1][3], bh0, bh1);
            MMA_BF16(acc[1][nt], ah[1][0], ah[1][1], ah[1][2], ah[1][3], bl0, bl1);
        }
        __syncthreads();   // protect buffers before next prefetch overwrites
    }

    // ---- epilogue: write fp32 partials ----
    float* gp = g_part + (size_t)blockIdx.y * (M_TOT * N_TOT);
#pragma unroll
    for (int mi = 0; mi < 2; mi++) {
        const int row0 = m0 + mg * 32 + mi * 16 + quad;
#pragma unroll
        for (int nt = 0; nt < 8; nt++) {
            const int col = ng * 64 + nt * 8 + tq * 2;
            *(float2*)(gp + (size_t)row0 * N_TOT + col) =
                make_float2(acc[mi][nt][0], acc[mi][nt][1]);
            *(float2*)(gp + (size_t)(row0 + 8) * N_TOT + col) =
                make_float2(acc[mi][nt][2], acc[mi][nt][3]);
        }
    }
}

// ---------------------------------------------------------------------------
// Mega kernel (512 threads): per-batch fused attention blocks + decoder.
// ---------------------------------------------------------------------------
#define RP 82

#define MEGA_FLOATS (128*RP + 128*RP + 128*96 + 32*128 + 128 + 3*80*32 + 32*RP)
#define MEGA_BYTES  (MEGA_FLOATS * 4)

__global__ __launch_bounds__(512) void mega_kernel(
    const float* __restrict__ Wq,   // [2][2][128][32]
    const float* __restrict__ Wkv,  // [2][2][128][64]
    const float* __restrict__ Wout, // [2][2][32][128]
    const float* __restrict__ Bout, // [2][2][128]
    const float* __restrict__ Bemb, // [128]
    const float* __restrict__ Wd,   // [10240]
    const float* __restrict__ bd,   // [1]
    float* __restrict__ out)
{
    extern __shared__ float smf[];
    float* hsT = smf;                   // [128][RP]
    float* otT = hsT + 128 * RP;        // [128][RP]
    float* wp  = otT + 128 * RP;        // [128][96]
    float* wo  = wp  + 128 * 96;        // [32][128]
    float* bo  = wo  + 32 * 128;        // [128]
    float* qs  = bo  + 128;             // [80][32]
    float* ks  = qs  + 80 * 32;
    float* vs  = ks  + 80 * 32;
    float* osT = vs  + 80 * 32;         // [32][RP]

    const int tid = threadIdx.x;
    const int b   = blockIdx.x;

    // ---- combine 8 GEMM partials + bias + leaky, transpose into smem ----
    {
        const size_t bo0 = (size_t)b * (T_ * C_ * D_);
        for (int v = tid; v < 2560; v += 512) {
            float4 s = make_float4(0.f, 0.f, 0.f, 0.f);
#pragma unroll
            for (int sp = 0; sp < KSPLIT; sp++) {
                float4 a = *(const float4*)(g_part + (size_t)sp * (M_TOT * N_TOT) + bo0 + v * 4);
                s.x += a.x; s.y += a.y; s.z += a.z; s.w += a.w;
            }
            const int r = v >> 5, d0 = (v & 31) * 4;
            float u0 = s.x + Bemb[d0 + 0];
            float u1 = s.y + Bemb[d0 + 1];
            float u2 = s.z + Bemb[d0 + 2];
            float u3 = s.w + Bemb[d0 + 3];
            hsT[(d0 + 0) * RP + r] = (u0 > 0.f) ? u0 : 0.2f * u0;
            hsT[(d0 + 1) * RP + r] = (u1 > 0.f) ? u1 : 0.2f * u1;
            hsT[(d0 + 2) * RP + r] = (u2 > 0.f) ? u2 : 0.2f * u2;
            hsT[(d0 + 3) * RP + r] = (u3 > 0.f) ? u3 : 0.2f * u3;
        }
    }
    __syncthreads();

    for (int blk = 0; blk < 2; blk++) {
        for (int axis = 0; axis < 2; axis++) {
            const int s = blk * 2 + axis;

            // ---- stage weights ----
            const float4* wq4  = (const float4*)(Wq  + s * 128 * 32);
            const float4* wkv4 = (const float4*)(Wkv + s * 128 * 64);
            for (int f = tid; f < 128 * 24; f += 512) {
                int d = f / 24, q4 = f - d * 24;
                float4 v = (q4 < 8) ? wq4[d * 8 + q4] : wkv4[d * 16 + (q4 - 8)];
                *(float4*)&wp[d * 96 + q4 * 4] = v;
            }
            const float4* wo4 = (const float4*)(Wout + s * 32 * 128);
            for (int f = tid; f < 1024; f += 512) ((float4*)wo)[f] = wo4[f];
            if (tid < 128) bo[tid] = Bout[s * 128 + tid];
            __syncthreads();

            // ---- qkv projection: 80 x 96, thread tile 4x4 (480 tasks) ----
            if (tid < 480) {
                const int rg = tid / 24;          // 0..19 (rows rg*4..+3)
                const int cg = tid - rg * 24;     // 0..23 (cols cg*4..+3)
                ull acc[2][4];
#pragma unroll
                for (int p = 0; p < 2; p++)
#pragma unroll
                    for (int j = 0; j < 4; j++) acc[p][j] = 0ull;

                const float* hb = &hsT[rg * 4];
                const float* wb = &wp[cg * 4];
#pragma unroll 4
                for (int d = 0; d < 128; d++) {
                    float2 a0 = *(const float2*)&hb[d * RP + 0];
                    float2 a1 = *(const float2*)&hb[d * RP + 2];
                    float4 w  = *(const float4*)&wb[d * 96];
                    ull ap0 = pack2(a0.x, a0.y), ap1 = pack2(a1.x, a1.y);
                    ull bp0 = pack2(w.x, w.x), bp1 = pack2(w.y, w.y);
                    ull bp2 = pack2(w.z, w.z), bp3 = pack2(w.w, w.w);
                    acc[0][0] = ffma2(ap0, bp0, acc[0][0]);
                    acc[0][1] = ffma2(ap0, bp1, acc[0][1]);
                    acc[0][2] = ffma2(ap0, bp2, acc[0][2]);
                    acc[0][3] = ffma2(ap0, bp3, acc[0][3]);
                    acc[1][0] = ffma2(ap1, bp0, acc[1][0]);
                    acc[1][1] = ffma2(ap1, bp1, acc[1][1]);
                    acc[1][2] = ffma2(ap1, bp2, acc[1][2]);
                    acc[1][3] = ffma2(ap1, bp3, acc[1][3]);
                }
                const int which = cg >> 3;   // 0=q, 1=k, 2=v
                float* dst = (which == 0) ? qs : (which == 1) ? ks : vs;
                const int lj = (cg & 7) * 4;
#pragma unroll
                for (int p = 0; p < 2; p++) {
                    const int r0 = rg * 4 + 2 * p;
#pragma unroll
                    for (int jc = 0; jc < 4; jc++) {
                        float2 v = unpack2(acc[p][jc]);
                        dst[r0 * 32 + lj + jc]       = v.x;
                        dst[(r0 + 1) * 32 + lj + jc] = v.y;
                    }
                }
            }
            __syncthreads();

            // ---- attention core (640 tasks) ----
            for (int o = tid; o < 640; o += 512) {
                if (axis == 0) {
                    const int t  = o % 20;
                    const int ch = o / 20;
                    const int c  = ch & 3, h = ch >> 2;
                    const int r  = t * 4 + c;
                    const float* qp = &qs[r * 32 + h * 4];
                    float p[20];
                    float mx = -1e30f;
#pragma unroll
                    for (int s2 = 0; s2 < 20; s2++) {
                        const float* kp = &ks[(s2 * 4 + c) * 32 + h * 4];
                        float d = (qp[0]*kp[0] + qp[1]*kp[1] + qp[2]*kp[2] + qp[3]*kp[3]) * 0.5f;
                        p[s2] = d;
                        mx = fmaxf(mx, d);
                    }
                    float sum = 0.f;
#pragma unroll
                    for (int s2 = 0; s2 < 20; s2++) { p[s2] = __expf(p[s2] - mx); sum += p[s2]; }
                    float inv = 1.f / sum;
                    float o0 = 0.f, o1 = 0.f, o2 = 0.f, o3 = 0.f;
#pragma unroll
                    for (int s2 = 0; s2 < 20; s2++) {
                        const float* vp = &vs[(s2 * 4 + c) * 32 + h * 4];
                        float w = p[s2] * inv;
                        o0 += w * vp[0]; o1 += w * vp[1]; o2 += w * vp[2]; o3 += w * vp[3];
                    }
                    osT[(h*4 + 0) * RP + r] = o0;
                    osT[(h*4 + 1) * RP + r] = o1;
                    osT[(h*4 + 2) * RP + r] = o2;
                    osT[(h*4 + 3) * RP + r] = o3;
                } else {
                    const int cq = o & 3;
                    const int h  = (o >> 2) & 7;
                    const int t  = o >> 5;
                    const int r  = t * 4 + cq;
                    const float* qp = &qs[r * 32 + h * 4];
                    float p[4];
                    float mx = -1e30f;
#pragma unroll
                    for (int s2 = 0; s2 < 4; s2++) {
                        const float* kp = &ks[(t * 4 + s2) * 32 + h * 4];
                        float d = (qp[0]*kp[0] + qp[1]*kp[1] + qp[2]*kp[2] + qp[3]*kp[3]) * 0.5f;
                        p[s2] = d;
                        mx = fmaxf(mx, d);
                    }
                    float sum = 0.f;
#pragma unroll
                    for (int s2 = 0; s2 < 4; s2++) { p[s2] = __expf(p[s2] - mx); sum += p[s2]; }
                    float inv = 1.f / sum;
                    float o0 = 0.f, o1 = 0.f, o2 = 0.f, o3 = 0.f;
#pragma unroll
                    for (int s2 = 0; s2 < 4; s2++) {
                        const float* vp = &vs[(t * 4 + s2) * 32 + h * 4];
                        float w = p[s2] * inv;
                        o0 += w * vp[0]; o1 += w * vp[1]; o2 += w * vp[2]; o3 += w * vp[3];
                    }
                    osT[(h*4 + 0) * RP + r] = o0;
                    osT[(h*4 + 1) * RP + r] = o1;
                    osT[(h*4 + 2) * RP + r] = o2;
                    osT[(h*4 + 3) * RP + r] = o3;
                }
            }
            __syncthreads();

            // ---- output projection: 80 x 128, thread tile 4x8 (320 tasks) ----
            if (tid < 320) {
                const int rg = tid >> 4;          // 0..19
                const int cg = tid & 15;          // cols cg*8..+7
                ull acc[2][8];
#pragma unroll
                for (int p = 0; p < 2; p++)
#pragma unroll
                    for (int jc = 0; jc < 8; jc++) acc[p][jc] = 0ull;

                const float* ob = &osT[rg * 4];
                const float* wb = &wo[cg * 8];
#pragma unroll
                for (int j = 0; j < 32; j++) {
                    float2 a0 = *(const float2*)&ob[j * RP + 0];
                    float2 a1 = *(const float2*)&ob[j * RP + 2];
                    float4 w0 = *(const float4*)&wb[j * 128];
                    float4 w1 = *(const float4*)&wb[j * 128 + 4];
                    ull ap[2] = { pack2(a0.x, a0.y), pack2(a1.x, a1.y) };
                    ull bp[8] = { pack2(w0.x, w0.x), pack2(w0.y, w0.y),
                                  pack2(w0.z, w0.z), pack2(w0.w, w0.w),
                                  pack2(w1.x, w1.x), pack2(w1.y, w1.y),
                                  pack2(w1.z, w1.z), pack2(w1.w, w1.w) };
#pragma unroll
                    for (int p = 0; p < 2; p++)
#pragma unroll
                        for (int jc = 0; jc < 8; jc++)
                            acc[p][jc] = ffma2(ap[p], bp[jc], acc[p][jc]);
                }
#pragma unroll
                for (int jc = 0; jc < 8; jc++) {
                    const int n = cg * 8 + jc;
                    const float bia = bo[n];
#pragma unroll
                    for (int p = 0; p < 2; p++) {
                        float2 v = unpack2(acc[p][jc]);
                        const int r0 = rg * 4 + 2 * p;
                        if (axis == 0) {
                            otT[n * RP + r0]     = v.x + bia;
                            otT[n * RP + r0 + 1] = v.y + bia;
                        } else {
                            float u0 = v.x + bia + otT[n * RP + r0];
                            float u1 = v.y + bia + otT[n * RP + r0 + 1];
                            hsT[n * RP + r0]     = (u0 > 0.f) ? u0 : 0.2f * u0;
                            hsT[n * RP + r0 + 1] = (u1 > 0.f) ? u1 : 0.2f * u1;
                        }
                    }
                }
            }
            __syncthreads();
        }
    }

    // ---- decoder ----
    float acc = 0.f;
    for (int f = tid; f < 10240; f += 512) {
        int r = f >> 7, d = f & 127;
        acc += hsT[d * RP + r] * Wd[f];
    }
#pragma unroll
    for (int off = 16; off; off >>= 1) acc += __shfl_down_sync(0xffffffffu, acc, off);
    if ((tid & 31) == 0) qs[tid >> 5] = acc;   // reuse qs as scratch (16 warps)
    __syncthreads();
    if (tid == 0) {
        float s = 0.f;
#pragma unroll
        for (int w = 0; w < 16; w++) s += qs[w];
        s += bd[0];
        out[b] = 1.f / (1.f + __expf(-s));
    }
}

// ---------------------------------------------------------------------------
// Launch
// ---------------------------------------------------------------------------
extern "C" void kernel_launch(void* const* d_in, const int* in_sizes, int n_in,
                              void* d_out, int out_size)
{
    const float* x     = (const float*)d_in[0];
    const float* n1    = (const float*)d_in[1];
    const float* n2    = (const float*)d_in[2];
    const float* W_emb = (const float*)d_in[3];
    const float* b_emb = (const float*)d_in[4];
    const float* Wq    = (const float*)d_in[5];
    const float* Wkv   = (const float*)d_in[6];
    const float* Wout  = (const float*)d_in[7];
    const float* bout  = (const float*)d_in[8];
    const float* W_dec = (const float*)d_in[9];
    const float* b_dec = (const float*)d_in[10];
    float* out = (float*)d_out;

    cudaFuncSetAttribute(emb_mma_kernel, cudaFuncAttributeMaxDynamicSharedMemorySize, EMB_SMEM);
    cudaFuncSetAttribute(mega_kernel, cudaFuncAttributeMaxDynamicSharedMemorySize, MEGA_BYTES);

    dim3 cg(K_TOT / 32, N_TOT / 32);
    conv_w_kernel<<<cg, 256>>>(W_emb);

    dim3 eg(M_TOT / MTILE, KSPLIT);
    emb_mma_kernel<<<eg, 256, EMB_SMEM>>>(x, n1, n2);

    mega_kernel<<<B_, 512, MEGA_BYTES>>>(Wq, Wkv, Wout, bout, b_emb, W_dec, b_dec, out);
}

// round 16
// speedup vs baseline: 2.7529x; 1.5570x over previous
#include <cuda_runtime.h>
#include <cuda_bf16.h>
#include <cstdint>

typedef unsigned long long ull;
typedef unsigned int uint;

// ---------------------------------------------------------------------------
// f32x2 packed FMA helpers (mega kernel)
// ---------------------------------------------------------------------------
__device__ __forceinline__ ull ffma2(ull a, ull b, ull c) {
    ull d;
    asm("fma.rn.f32x2 %0, %1, %2, %3;" : "=l"(d) : "l"(a), "l"(b), "l"(c));
    return d;
}
__device__ __forceinline__ ull pack2(float lo, float hi) {
    ull d;
    asm("mov.b64 %0, {%1, %2};" : "=l"(d) : "f"(lo), "f"(hi));
    return d;
}
__device__ __forceinline__ float2 unpack2(ull v) {
    float2 r;
    asm("mov.b64 {%0, %1}, %2;" : "=f"(r.x), "=f"(r.y) : "l"(v));
    return r;
}

// pack 2 fp32 -> bf16x2 (v0 -> lower half, v1 -> upper half)
__device__ __forceinline__ uint pbf(float v0, float v1) {
    uint r;
    asm("cvt.rn.bf16x2.f32 %0, %1, %2;" : "=r"(r) : "f"(v1), "f"(v0));
    return r;
}

// ---------------------------------------------------------------------------
// Problem constants
// ---------------------------------------------------------------------------
#define B_    128
#define T_    20
#define C_    4
#define HW_   4096
#define D_    128

#define M_TOT (B_ * T_ * C_)   // 10240
#define K_TOT HW_              // 4096
#define N_TOT D_               // 128

#define KSPLIT 4
#define KSEG   (K_TOT / KSPLIT)   // 1024
#define MTILE  128

#define KC     32                 // K per chunk
#define NCHUNK (KSEG / KC)        // 32

// scratch (device globals; no allocation allowed)
__device__ float g_part[KSPLIT * M_TOT * N_TOT];             // 20 MB
__device__ __align__(16) __nv_bfloat16 g_wT[N_TOT * K_TOT];  // W^T bf16, K-major

// ---------------------------------------------------------------------------
// bf16 MMA (m16n8k16, fp32 accumulate) — portable PTX, HMMA on sm_103
// ---------------------------------------------------------------------------
#define MMA_BF16(d, a0, a1, a2, a3, b0, b1)                                   \
    asm volatile(                                                             \
        "mma.sync.aligned.m16n8k16.row.col.f32.bf16.bf16.f32 "                \
        "{%0,%1,%2,%3},{%4,%5,%6,%7},{%8,%9},{%0,%1,%2,%3};"                  \
        : "+f"((d)[0]), "+f"((d)[1]), "+f"((d)[2]), "+f"((d)[3])              \
        : "r"(a0), "r"(a1), "r"(a2), "r"(a3), "r"(b0), "r"(b1))

__device__ __forceinline__ void cp_async16(void* dst_smem, const void* src_gmem) {
    uint ds = (uint)__cvta_generic_to_shared(dst_smem);
    asm volatile("cp.async.cg.shared.global [%0], [%1], 16;"
                 :: "r"(ds), "l"(__cvta_generic_to_global(src_gmem)) : "memory");
}
__device__ __forceinline__ void cp_async_commit() {
    asm volatile("cp.async.commit_group;" ::: "memory");
}
__device__ __forceinline__ void cp_async_wait1() {
    asm volatile("cp.async.wait_group 1;" ::: "memory");
}
__device__ __forceinline__ void cp_async_wait0() {
    asm volatile("cp.async.wait_group 0;" ::: "memory");
}

// ---------------------------------------------------------------------------
// Kernel 0: convert + transpose W_emb into K-major bf16 (smem-tiled)
// ---------------------------------------------------------------------------
__global__ __launch_bounds__(256) void conv_w_kernel(const float* __restrict__ W) {
    __shared__ float ts[32][33];
    const int tid = threadIdx.x;
    const int j = tid & 31, i0 = tid >> 5;
    const int k0 = blockIdx.x * 32, n0 = blockIdx.y * 32;

#pragma unroll
    for (int r = 0; r < 4; r++) {
        const int i = i0 + r * 8;
        ts[i][j] = W[(size_t)(k0 + i) * N_TOT + n0 + j];
    }
    __syncthreads();

#pragma unroll
    for (int r = 0; r < 4; r++) {
        const int n = i0 + r * 8;
        g_wT[(size_t)(n0 + n) * K_TOT + k0 + j] = __float2bfloat16(ts[j][n]);
    }
}

// ---------------------------------------------------------------------------
// Kernel 1: HMMA embedding GEMM, fully async, single bf16 MMA.
//   A = bf16(x) staged fp32 via cp.async; W = bf16 preconverted.
//   grid (80, 4), 256 threads = 8 warps tiled 4m x 2n, KC=32, occ 2/SM.
//   A pitch 160B (conflict-free LDS.64), B pitch 80B (conflict-free LDS.32).
// ---------------------------------------------------------------------------
#define A_PITCH 160
#define A_BUF_B (MTILE * A_PITCH)   // 20480
#define B_PITCH 80
#define B_BUF_B (N_TOT * B_PITCH)   // 10240
#define OFF_BST (2 * A_BUF_B)       // 40960
#define EMB_SMEM (2 * A_BUF_B + 2 * B_BUF_B)   // 61440

__global__ __launch_bounds__(256, 2) void emb_mma_kernel(const float* __restrict__ X)
{
    extern __shared__ unsigned char sm[];

    const int tid  = threadIdx.x;
    const int wid  = tid >> 5;
    const int lane = tid & 31;
    const int quad = lane >> 2;      // 0..7
    const int tq   = lane & 3;       // 0..3
    const int m0   = blockIdx.x * MTILE;
    const int ks0  = blockIdx.y * KSEG;

    const int mg = wid & 3;          // m-group: rows mg*32 .. +31
    const int ng = wid >> 2;         // n-group: cols ng*64 .. +63

    float acc[2][8][4];
#pragma unroll
    for (int mi = 0; mi < 2; mi++)
#pragma unroll
        for (int nt = 0; nt < 8; nt++)
#pragma unroll
            for (int j = 0; j < 4; j++) acc[mi][nt][j] = 0.f;

    // ---- producer: cp.async one chunk (A fp32 1024 tasks + B bf16 512) ----
    auto prefetch = [&](int chunk, int buf) {
        const long kb = (long)ks0 + chunk * KC;
#pragma unroll
        for (int r = 0; r < 4; r++) {
            const int idx = tid + 256 * r;
            const int row = idx >> 3, seg = idx & 7;
            cp_async16(sm + (size_t)buf * A_BUF_B + row * A_PITCH + seg * 16,
                       X + (long)(m0 + row) * K_TOT + kb + seg * 4);
        }
#pragma unroll
        for (int r = 0; r < 2; r++) {
            const int idx = tid + 256 * r;
            const int n = idx >> 2, seg = idx & 3;
            cp_async16(sm + OFF_BST + (size_t)buf * B_BUF_B + n * B_PITCH + seg * 16,
                       (const char*)(g_wT + (size_t)n * K_TOT + kb) + seg * 16);
        }
        cp_async_commit();
    };

    prefetch(0, 0);

    for (int i = 0; i < NCHUNK; i++) {
        const int buf = i & 1;
        if (i + 1 < NCHUNK) prefetch(i + 1, buf ^ 1);

        if (i + 1 < NCHUNK) cp_async_wait1(); else cp_async_wait0();
        __syncthreads();

        // ---- build A fragments (round to bf16) ----
        const unsigned char* As = sm + (size_t)buf * A_BUF_B;
        uint a[2][2][4];   // [mi][ks][slot]
#pragma unroll
        for (int mi = 0; mi < 2; mi++) {
            const int wrm = mg * 32 + mi * 16 + quad;
#pragma unroll
            for (int ks = 0; ks < 2; ks++) {
#pragma unroll
                for (int s = 0; s < 4; s++) {
                    const int row = wrm + (s & 1) * 8;
                    const int off = row * A_PITCH + ks * 64 + tq * 8 + (s >> 1) * 32;
                    float2 v = *(const float2*)(As + off);
                    a[mi][ks][s] = pbf(v.x, v.y);
                }
            }
        }

        // ---- MMA: 2 ksteps x 8 n-tiles x 2 m-tiles ----
        const unsigned char* Bs = sm + OFF_BST + (size_t)buf * B_BUF_B;
#pragma unroll
        for (int ks = 0; ks < 2; ks++) {
#pragma unroll
            for (int nt = 0; nt < 8; nt++) {
                const int n = ng * 64 + nt * 8 + quad;
                const int nb = n * B_PITCH + ks * 32 + tq * 4;
                uint b0 = *(const uint*)(Bs + nb);
                uint b1 = *(const uint*)(Bs + nb + 16);
                MMA_BF16(acc[0][nt], a[0][ks][0], a[0][ks][1], a[0][ks][2], a[0][ks][3], b0, b1);
                MMA_BF16(acc[1][nt], a[1][ks][0], a[1][ks][1], a[1][ks][2], a[1][ks][3], b0, b1);
            }
        }
        __syncthreads();   // protect buffers before next prefetch overwrites
    }

    // ---- epilogue: write fp32 partials ----
    float* gp = g_part + (size_t)blockIdx.y * (M_TOT * N_TOT);
#pragma unroll
    for (int mi = 0; mi < 2; mi++) {
        const int row0 = m0 + mg * 32 + mi * 16 + quad;
#pragma unroll
        for (int nt = 0; nt < 8; nt++) {
            const int col = ng * 64 + nt * 8 + tq * 2;
            *(float2*)(gp + (size_t)row0 * N_TOT + col) =
                make_float2(acc[mi][nt][0], acc[mi][nt][1]);
            *(float2*)(gp + (size_t)(row0 + 8) * N_TOT + col) =
                make_float2(acc[mi][nt][2], acc[mi][nt][3]);
        }
    }
}

// ---------------------------------------------------------------------------
// Mega kernel (512 threads): per-batch fused attention blocks + decoder.
// ---------------------------------------------------------------------------
#define RP 82

#define MEGA_FLOATS (128*RP + 128*RP + 128*96 + 32*128 + 128 + 3*80*32 + 32*RP)
#define MEGA_BYTES  (MEGA_FLOATS * 4)

__global__ __launch_bounds__(512) void mega_kernel(
    const float* __restrict__ Wq,   // [2][2][128][32]
    const float* __restrict__ Wkv,  // [2][2][128][64]
    const float* __restrict__ Wout, // [2][2][32][128]
    const float* __restrict__ Bout, // [2][2][128]
    const float* __restrict__ Bemb, // [128]
    const float* __restrict__ Wd,   // [10240]
    const float* __restrict__ bd,   // [1]
    float* __restrict__ out)
{
    extern __shared__ float smf[];
    float* hsT = smf;                   // [128][RP]
    float* otT = hsT + 128 * RP;        // [128][RP]
    float* wp  = otT + 128 * RP;        // [128][96]
    float* wo  = wp  + 128 * 96;        // [32][128]
    float* bo  = wo  + 32 * 128;        // [128]
    float* qs  = bo  + 128;             // [80][32]
    float* ks  = qs  + 80 * 32;
    float* vs  = ks  + 80 * 32;
    float* osT = vs  + 80 * 32;         // [32][RP]

    const int tid = threadIdx.x;
    const int b   = blockIdx.x;

    // ---- combine GEMM partials + bias + leaky, transpose into smem ----
    {
        const size_t bo0 = (size_t)b * (T_ * C_ * D_);
        for (int v = tid; v < 2560; v += 512) {
            float4 s = make_float4(0.f, 0.f, 0.f, 0.f);
#pragma unroll
            for (int sp = 0; sp < KSPLIT; sp++) {
                float4 a = *(const float4*)(g_part + (size_t)sp * (M_TOT * N_TOT) + bo0 + v * 4);
                s.x += a.x; s.y += a.y; s.z += a.z; s.w += a.w;
            }
            const int r = v >> 5, d0 = (v & 31) * 4;
            float u0 = s.x + Bemb[d0 + 0];
            float u1 = s.y + Bemb[d0 + 1];
            float u2 = s.z + Bemb[d0 + 2];
            float u3 = s.w + Bemb[d0 + 3];
            hsT[(d0 + 0) * RP + r] = (u0 > 0.f) ? u0 : 0.2f * u0;
            hsT[(d0 + 1) * RP + r] = (u1 > 0.f) ? u1 : 0.2f * u1;
            hsT[(d0 + 2) * RP + r] = (u2 > 0.f) ? u2 : 0.2f * u2;
            hsT[(d0 + 3) * RP + r] = (u3 > 0.f) ? u3 : 0.2f * u3;
        }
    }
    __syncthreads();

    for (int blk = 0; blk < 2; blk++) {
        for (int axis = 0; axis < 2; axis++) {
            const int s = blk * 2 + axis;

            // ---- stage weights ----
            const float4* wq4  = (const float4*)(Wq  + s * 128 * 32);
            const float4* wkv4 = (const float4*)(Wkv + s * 128 * 64);
            for (int f = tid; f < 128 * 24; f += 512) {
                int d = f / 24, q4 = f - d * 24;
                float4 v = (q4 < 8) ? wq4[d * 8 + q4] : wkv4[d * 16 + (q4 - 8)];
                *(float4*)&wp[d * 96 + q4 * 4] = v;
            }
            const float4* wo4 = (const float4*)(Wout + s * 32 * 128);
            for (int f = tid; f < 1024; f += 512) ((float4*)wo)[f] = wo4[f];
            if (tid < 128) bo[tid] = Bout[s * 128 + tid];
            __syncthreads();

            // ---- qkv projection: 80 x 96, thread tile 4x4 (480 tasks) ----
            if (tid < 480) {
                const int rg = tid / 24;          // 0..19 (rows rg*4..+3)
                const int cg = tid - rg * 24;     // 0..23 (cols cg*4..+3)
                ull acc[2][4];
#pragma unroll
                for (int p = 0; p < 2; p++)
#pragma unroll
                    for (int j = 0; j < 4; j++) acc[p][j] = 0ull;

                const float* hb = &hsT[rg * 4];
                const float* wb = &wp[cg * 4];
#pragma unroll 4
                for (int d = 0; d < 128; d++) {
                    float2 a0 = *(const float2*)&hb[d * RP + 0];
                    float2 a1 = *(const float2*)&hb[d * RP + 2];
                    float4 w  = *(const float4*)&wb[d * 96];
                    ull ap0 = pack2(a0.x, a0.y), ap1 = pack2(a1.x, a1.y);
                    ull bp0 = pack2(w.x, w.x), bp1 = pack2(w.y, w.y);
                    ull bp2 = pack2(w.z, w.z), bp3 = pack2(w.w, w.w);
                    acc[0][0] = ffma2(ap0, bp0, acc[0][0]);
                    acc[0][1] = ffma2(ap0, bp1, acc[0][1]);
                    acc[0][2] = ffma2(ap0, bp2, acc[0][2]);
                    acc[0][3] = ffma2(ap0, bp3, acc[0][3]);
                    acc[1][0] = ffma2(ap1, bp0, acc[1][0]);
                    acc[1][1] = ffma2(ap1, bp1, acc[1][1]);
                    acc[1][2] = ffma2(ap1, bp2, acc[1][2]);
                    acc[1][3] = ffma2(ap1, bp3, acc[1][3]);
                }
                const int which = cg >> 3;   // 0=q, 1=k, 2=v
                float* dst = (which == 0) ? qs : (which == 1) ? ks : vs;
                const int lj = (cg & 7) * 4;
#pragma unroll
                for (int p = 0; p < 2; p++) {
                    const int r0 = rg * 4 + 2 * p;
#pragma unroll
                    for (int jc = 0; jc < 4; jc++) {
                        float2 v = unpack2(acc[p][jc]);
                        dst[r0 * 32 + lj + jc]       = v.x;
                        dst[(r0 + 1) * 32 + lj + jc] = v.y;
                    }
                }
            }
            __syncthreads();

            // ---- attention core (640 tasks) ----
            for (int o = tid; o < 640; o += 512) {
                if (axis == 0) {
                    const int t  = o % 20;
                    const int ch = o / 20;
                    const int c  = ch & 3, h = ch >> 2;
                    const int r  = t * 4 + c;
                    const float* qp = &qs[r * 32 + h * 4];
                    float p[20];
                    float mx = -1e30f;
#pragma unroll
                    for (int s2 = 0; s2 < 20; s2++) {
                        const float* kp = &ks[(s2 * 4 + c) * 32 + h * 4];
                        float d = (qp[0]*kp[0] + qp[1]*kp[1] + qp[2]*kp[2] + qp[3]*kp[3]) * 0.5f;
                        p[s2] = d;
                        mx = fmaxf(mx, d);
                    }
                    float sum = 0.f;
#pragma unroll
                    for (int s2 = 0; s2 < 20; s2++) { p[s2] = __expf(p[s2] - mx); sum += p[s2]; }
                    float inv = 1.f / sum;
                    float o0 = 0.f, o1 = 0.f, o2 = 0.f, o3 = 0.f;
#pragma unroll
                    for (int s2 = 0; s2 < 20; s2++) {
                        const float* vp = &vs[(s2 * 4 + c) * 32 + h * 4];
                        float w = p[s2] * inv;
                        o0 += w * vp[0]; o1 += w * vp[1]; o2 += w * vp[2]; o3 += w * vp[3];
                    }
                    osT[(h*4 + 0) * RP + r] = o0;
                    osT[(h*4 + 1) * RP + r] = o1;
                    osT[(h*4 + 2) * RP + r] = o2;
                    osT[(h*4 + 3) * RP + r] = o3;
                } else {
                    const int cq = o & 3;
                    const int h  = (o >> 2) & 7;
                    const int t  = o >> 5;
                    const int r  = t * 4 + cq;
                    const float* qp = &qs[r * 32 + h * 4];
                    float p[4];
                    float mx = -1e30f;
#pragma unroll
                    for (int s2 = 0; s2 < 4; s2++) {
                        const float* kp = &ks[(t * 4 + s2) * 32 + h * 4];
                        float d = (qp[0]*kp[0] + qp[1]*kp[1] + qp[2]*kp[2] + qp[3]*kp[3]) * 0.5f;
                        p[s2] = d;
                        mx = fmaxf(mx, d);
                    }
                    float sum = 0.f;
#pragma unroll
                    for (int s2 = 0; s2 < 4; s2++) { p[s2] = __expf(p[s2] - mx); sum += p[s2]; }
                    float inv = 1.f / sum;
                    float o0 = 0.f, o1 = 0.f, o2 = 0.f, o3 = 0.f;
#pragma unroll
                    for (int s2 = 0; s2 < 4; s2++) {
                        const float* vp = &vs[(t * 4 + s2) * 32 + h * 4];
                        float w = p[s2] * inv;
                        o0 += w * vp[0]; o1 += w * vp[1]; o2 += w * vp[2]; o3 += w * vp[3];
                    }
                    osT[(h*4 + 0) * RP + r] = o0;
                    osT[(h*4 + 1) * RP + r] = o1;
                    osT[(h*4 + 2) * RP + r] = o2;
                    osT[(h*4 + 3) * RP + r] = o3;
                }
            }
            __syncthreads();

            // ---- output projection: 80 x 128, thread tile 4x8 (320 tasks) ----
            if (tid < 320) {
                const int rg = tid >> 4;          // 0..19
                const int cg = tid & 15;          // cols cg*8..+7
                ull acc[2][8];
#pragma unroll
                for (int p = 0; p < 2; p++)
#pragma unroll
                    for (int jc = 0; jc < 8; jc++) acc[p][jc] = 0ull;

                const float* ob = &osT[rg * 4];
                const float* wb = &wo[cg * 8];
#pragma unroll
                for (int j = 0; j < 32; j++) {
                    float2 a0 = *(const float2*)&ob[j * RP + 0];
                    float2 a1 = *(const float2*)&ob[j * RP + 2];
                    float4 w0 = *(const float4*)&wb[j * 128];
                    float4 w1 = *(const float4*)&wb[j * 128 + 4];
                    ull ap[2] = { pack2(a0.x, a0.y), pack2(a1.x, a1.y) };
                    ull bp[8] = { pack2(w0.x, w0.x), pack2(w0.y, w0.y),
                                  pack2(w0.z, w0.z), pack2(w0.w, w0.w),
                                  pack2(w1.x, w1.x), pack2(w1.y, w1.y),
                                  pack2(w1.z, w1.z), pack2(w1.w, w1.w) };
#pragma unroll
                    for (int p = 0; p < 2; p++)
#pragma unroll
                        for (int jc = 0; jc < 8; jc++)
                            acc[p][jc] = ffma2(ap[p], bp[jc], acc[p][jc]);
                }
#pragma unroll
                for (int jc = 0; jc < 8; jc++) {
                    const int n = cg * 8 + jc;
                    const float bia = bo[n];
#pragma unroll
                    for (int p = 0; p < 2; p++) {
                        float2 v = unpack2(acc[p][jc]);
                        const int r0 = rg * 4 + 2 * p;
                        if (axis == 0) {
                            otT[n * RP + r0]     = v.x + bia;
                            otT[n * RP + r0 + 1] = v.y + bia;
                        } else {
                            float u0 = v.x + bia + otT[n * RP + r0];
                            float u1 = v.y + bia + otT[n * RP + r0 + 1];
                            hsT[n * RP + r0]     = (u0 > 0.f) ? u0 : 0.2f * u0;
                            hsT[n * RP + r0 + 1] = (u1 > 0.f) ? u1 : 0.2f * u1;
                        }
                    }
                }
            }
            __syncthreads();
        }
    }

    // ---- decoder ----
    float acc = 0.f;
    for (int f = tid; f < 10240; f += 512) {
        int r = f >> 7, d = f & 127;
        acc += hsT[d * RP + r] * Wd[f];
    }
#pragma unroll
    for (int off = 16; off; off >>= 1) acc += __shfl_down_sync(0xffffffffu, acc, off);
    if ((tid & 31) == 0) qs[tid >> 5] = acc;   // reuse qs as scratch (16 warps)
    __syncthreads();
    if (tid == 0) {
        float s = 0.f;
#pragma unroll
        for (int w = 0; w < 16; w++) s += qs[w];
        s += bd[0];
        out[b] = 1.f / (1.f + __expf(-s));
    }
}

// ---------------------------------------------------------------------------
// Launch
// ---------------------------------------------------------------------------
extern "C" void kernel_launch(void* const* d_in, const int* in_sizes, int n_in,
                              void* d_out, int out_size)
{
    const float* x     = (const float*)d_in[0];
    const float* W_emb = (const float*)d_in[3];
    const float* b_emb = (const float*)d_in[4];
    const float* Wq    = (const float*)d_in[5];
    const float* Wkv   = (const float*)d_in[6];
    const float* Wout  = (const float*)d_in[7];
    const float* bout  = (const float*)d_in[8];
    const float* W_dec = (const float*)d_in[9];
    const float* b_dec = (const float*)d_in[10];
    float* out = (float*)d_out;

    cudaFuncSetAttribute(emb_mma_kernel, cudaFuncAttributeMaxDynamicSharedMemorySize, EMB_SMEM);
    cudaFuncSetAttribute(mega_kernel, cudaFuncAttributeMaxDynamicSharedMemorySize, MEGA_BYTES);

    dim3 cg(K_TOT / 32, N_TOT / 32);
    conv_w_kernel<<<cg, 256>>>(W_emb);

    dim3 eg(M_TOT / MTILE, KSPLIT);
    emb_mma_kernel<<<eg, 256, EMB_SMEM>>>(x);

    mega_kernel<<<B_, 512, MEGA_BYTES>>>(Wq, Wkv, Wout, bout, b_emb, W_dec, b_dec, out);
}

// round 17
// speedup vs baseline: 3.0245x; 1.0986x over previous
#include <cuda_runtime.h>
#include <cuda_bf16.h>
#include <cstdint>

typedef unsigned long long ull;
typedef unsigned int uint;

// ---------------------------------------------------------------------------
// f32x2 packed FMA helpers
// ---------------------------------------------------------------------------
__device__ __forceinline__ ull ffma2(ull a, ull b, ull c) {
    ull d;
    asm("fma.rn.f32x2 %0, %1, %2, %3;" : "=l"(d) : "l"(a), "l"(b), "l"(c));
    return d;
}
__device__ __forceinline__ ull pack2(float lo, float hi) {
    ull d;
    asm("mov.b64 %0, {%1, %2};" : "=l"(d) : "f"(lo), "f"(hi));
    return d;
}
__device__ __forceinline__ float2 unpack2(ull v) {
    float2 r;
    asm("mov.b64 {%0, %1}, %2;" : "=f"(r.x), "=f"(r.y) : "l"(v));
    return r;
}

// pack 2 fp32 -> bf16x2 (v0 -> lower half, v1 -> upper half)
__device__ __forceinline__ uint pbf(float v0, float v1) {
    uint r;
    asm("cvt.rn.bf16x2.f32 %0, %1, %2;" : "=r"(r) : "f"(v1), "f"(v0));
    return r;
}
// bf16x2 halves -> fp32
__device__ __forceinline__ float blo(uint u) { return __uint_as_float(u << 16); }
__device__ __forceinline__ float bhi(uint u) { return __uint_as_float(u & 0xffff0000u); }

// ---------------------------------------------------------------------------
// Problem constants
// ---------------------------------------------------------------------------
#define B_    128
#define T_    20
#define C_    4
#define HW_   4096
#define D_    128

#define M_TOT (B_ * T_ * C_)   // 10240
#define K_TOT HW_              // 4096
#define N_TOT D_               // 128

#define KSPLIT 4
#define KSEG   (K_TOT / KSPLIT)   // 1024
#define MTILE  128

#define KC     32                 // K per chunk
#define NCHUNK (KSEG / KC)        // 32

// scratch (device globals; no allocation allowed)
__device__ float g_part[KSPLIT * M_TOT * N_TOT];             // 20 MB
__device__ __align__(16) __nv_bfloat16 g_wT[N_TOT * K_TOT];  // W^T bf16, K-major

// ---------------------------------------------------------------------------
// bf16 MMA (m16n8k16, fp32 accumulate) — portable PTX, HMMA on sm_103
// ---------------------------------------------------------------------------
#define MMA_BF16(d, a0, a1, a2, a3, b0, b1)                                   \
    asm volatile(                                                             \
        "mma.sync.aligned.m16n8k16.row.col.f32.bf16.bf16.f32 "                \
        "{%0,%1,%2,%3},{%4,%5,%6,%7},{%8,%9},{%0,%1,%2,%3};"                  \
        : "+f"((d)[0]), "+f"((d)[1]), "+f"((d)[2]), "+f"((d)[3])              \
        : "r"(a0), "r"(a1), "r"(a2), "r"(a3), "r"(b0), "r"(b1))

__device__ __forceinline__ void cp_async16(void* dst_smem, const void* src_gmem) {
    uint ds = (uint)__cvta_generic_to_shared(dst_smem);
    asm volatile("cp.async.cg.shared.global [%0], [%1], 16;"
                 :: "r"(ds), "l"(__cvta_generic_to_global(src_gmem)) : "memory");
}
__device__ __forceinline__ void cp_async_commit() {
    asm volatile("cp.async.commit_group;" ::: "memory");
}
__device__ __forceinline__ void cp_async_wait1() {
    asm volatile("cp.async.wait_group 1;" ::: "memory");
}
__device__ __forceinline__ void cp_async_wait0() {
    asm volatile("cp.async.wait_group 0;" ::: "memory");
}

// ---------------------------------------------------------------------------
// Kernel 0: convert + transpose W_emb into K-major bf16 (smem-tiled)
// ---------------------------------------------------------------------------
__global__ __launch_bounds__(256) void conv_w_kernel(const float* __restrict__ W) {
    __shared__ float ts[32][33];
    const int tid = threadIdx.x;
    const int j = tid & 31, i0 = tid >> 5;
    const int k0 = blockIdx.x * 32, n0 = blockIdx.y * 32;

#pragma unroll
    for (int r = 0; r < 4; r++) {
        const int i = i0 + r * 8;
        ts[i][j] = W[(size_t)(k0 + i) * N_TOT + n0 + j];
    }
    __syncthreads();

#pragma unroll
    for (int r = 0; r < 4; r++) {
        const int n = i0 + r * 8;
        g_wT[(size_t)(n0 + n) * K_TOT + k0 + j] = __float2bfloat16(ts[j][n]);
    }
}

// ---------------------------------------------------------------------------
// Kernel 1: HMMA embedding GEMM (unchanged from R16 winner)
// ---------------------------------------------------------------------------
#define A_PITCH 160
#define A_BUF_B (MTILE * A_PITCH)   // 20480
#define B_PITCH 80
#define B_BUF_B (N_TOT * B_PITCH)   // 10240
#define OFF_BST (2 * A_BUF_B)       // 40960
#define EMB_SMEM (2 * A_BUF_B + 2 * B_BUF_B)   // 61440

__global__ __launch_bounds__(256, 2) void emb_mma_kernel(const float* __restrict__ X)
{
    extern __shared__ unsigned char sm[];

    const int tid  = threadIdx.x;
    const int wid  = tid >> 5;
    const int lane = tid & 31;
    const int quad = lane >> 2;
    const int tq   = lane & 3;
    const int m0   = blockIdx.x * MTILE;
    const int ks0  = blockIdx.y * KSEG;

    const int mg = wid & 3;
    const int ng = wid >> 2;

    float acc[2][8][4];
#pragma unroll
    for (int mi = 0; mi < 2; mi++)
#pragma unroll
        for (int nt = 0; nt < 8; nt++)
#pragma unroll
            for (int j = 0; j < 4; j++) acc[mi][nt][j] = 0.f;

    auto prefetch = [&](int chunk, int buf) {
        const long kb = (long)ks0 + chunk * KC;
#pragma unroll
        for (int r = 0; r < 4; r++) {
            const int idx = tid + 256 * r;
            const int row = idx >> 3, seg = idx & 7;
            cp_async16(sm + (size_t)buf * A_BUF_B + row * A_PITCH + seg * 16,
                       X + (long)(m0 + row) * K_TOT + kb + seg * 4);
        }
#pragma unroll
        for (int r = 0; r < 2; r++) {
            const int idx = tid + 256 * r;
            const int n = idx >> 2, seg = idx & 3;
            cp_async16(sm + OFF_BST + (size_t)buf * B_BUF_B + n * B_PITCH + seg * 16,
                       (const char*)(g_wT + (size_t)n * K_TOT + kb) + seg * 16);
        }
        cp_async_commit();
    };

    prefetch(0, 0);

    for (int i = 0; i < NCHUNK; i++) {
        const int buf = i & 1;
        if (i + 1 < NCHUNK) prefetch(i + 1, buf ^ 1);

        if (i + 1 < NCHUNK) cp_async_wait1(); else cp_async_wait0();
        __syncthreads();

        const unsigned char* As = sm + (size_t)buf * A_BUF_B;
        uint a[2][2][4];
#pragma unroll
        for (int mi = 0; mi < 2; mi++) {
            const int wrm = mg * 32 + mi * 16 + quad;
#pragma unroll
            for (int ks = 0; ks < 2; ks++) {
#pragma unroll
                for (int s = 0; s < 4; s++) {
                    const int row = wrm + (s & 1) * 8;
                    const int off = row * A_PITCH + ks * 64 + tq * 8 + (s >> 1) * 32;
                    float2 v = *(const float2*)(As + off);
                    a[mi][ks][s] = pbf(v.x, v.y);
                }
            }
        }

        const unsigned char* Bs = sm + OFF_BST + (size_t)buf * B_BUF_B;
#pragma unroll
        for (int ks = 0; ks < 2; ks++) {
#pragma unroll
            for (int nt = 0; nt < 8; nt++) {
                const int n = ng * 64 + nt * 8 + quad;
                const int nb = n * B_PITCH + ks * 32 + tq * 4;
                uint b0 = *(const uint*)(Bs + nb);
                uint b1 = *(const uint*)(Bs + nb + 16);
                MMA_BF16(acc[0][nt], a[0][ks][0], a[0][ks][1], a[0][ks][2], a[0][ks][3], b0, b1);
                MMA_BF16(acc[1][nt], a[1][ks][0], a[1][ks][1], a[1][ks][2], a[1][ks][3], b0, b1);
            }
        }
        __syncthreads();
    }

    float* gp = g_part + (size_t)blockIdx.y * (M_TOT * N_TOT);
#pragma unroll
    for (int mi = 0; mi < 2; mi++) {
        const int row0 = m0 + mg * 32 + mi * 16 + quad;
#pragma unroll
        for (int nt = 0; nt < 8; nt++) {
            const int col = ng * 64 + nt * 8 + tq * 2;
            *(float2*)(gp + (size_t)row0 * N_TOT + col) =
                make_float2(acc[mi][nt][0], acc[mi][nt][1]);
            *(float2*)(gp + (size_t)(row0 + 8) * N_TOT + col) =
                make_float2(acc[mi][nt][2], acc[mi][nt][3]);
        }
    }
}

// ---------------------------------------------------------------------------
// Mega kernel (512 threads): per-batch, BOTH axes per layer computed
// concurrently; weights staged as packed bf16x2; fused out-projection.
// smem layout (words):
//   hsT   [128][82]              10496  fp32
//   wpT   [128][48]  (bf16x2)     6144
//   wpC   [128][48]               6144
//   woT   [32][64]   (bf16x2)     2048
//   woC   [32][64]                2048
//   boT/boC [128] each             256
//   qsT ksT vsT qsC ksC vsC [80][32] x6 = 15360
//   osTT osTC [32][82] x2 = 5248
// total 47744 words = 190976 B
// ---------------------------------------------------------------------------
#define RP 82
#define MEGA_BYTES (47744 * 4)

__global__ __launch_bounds__(512) void mega_kernel(
    const float* __restrict__ Wq,   // [2][2][128][32]
    const float* __restrict__ Wkv,  // [2][2][128][64]
    const float* __restrict__ Wout, // [2][2][32][128]
    const float* __restrict__ Bout, // [2][2][128]
    const float* __restrict__ Bemb, // [128]
    const float* __restrict__ Wd,   // [10240]
    const float* __restrict__ bd,   // [1]
    float* __restrict__ out)
{
    extern __shared__ float smf[];
    float* hsT  = smf;                         // [128][RP]
    uint*  wpT  = (uint*)(hsT + 128 * RP);     // [128][48]
    uint*  wpC  = wpT + 6144;
    uint*  woT  = wpC + 6144;                  // [32][64]
    uint*  woC  = woT + 2048;
    float* boT  = (float*)(woC + 2048);
    float* boC  = boT + 128;
    float* qsT  = boC + 128;                   // [80][32] x6
    float* ksT  = qsT + 2560;
    float* vsT  = ksT + 2560;
    float* qsC  = vsT + 2560;
    float* ksC  = qsC + 2560;
    float* vsC  = ksC + 2560;
    float* osTT = vsC + 2560;                  // [32][RP]
    float* osTC = osTT + 32 * RP;

    const int tid = threadIdx.x;
    const int b   = blockIdx.x;

    // ---- combine GEMM partials + bias + leaky, transpose into smem ----
    {
        const size_t bo0 = (size_t)b * (T_ * C_ * D_);
        for (int v = tid; v < 2560; v += 512) {
            float4 s = make_float4(0.f, 0.f, 0.f, 0.f);
#pragma unroll
            for (int sp = 0; sp < KSPLIT; sp++) {
                float4 a = *(const float4*)(g_part + (size_t)sp * (M_TOT * N_TOT) + bo0 + v * 4);
                s.x += a.x; s.y += a.y; s.z += a.z; s.w += a.w;
            }
            const int r = v >> 5, d0 = (v & 31) * 4;
            float u0 = s.x + Bemb[d0 + 0];
            float u1 = s.y + Bemb[d0 + 1];
            float u2 = s.z + Bemb[d0 + 2];
            float u3 = s.w + Bemb[d0 + 3];
            hsT[(d0 + 0) * RP + r] = (u0 > 0.f) ? u0 : 0.2f * u0;
            hsT[(d0 + 1) * RP + r] = (u1 > 0.f) ? u1 : 0.2f * u1;
            hsT[(d0 + 2) * RP + r] = (u2 > 0.f) ? u2 : 0.2f * u2;
            hsT[(d0 + 3) * RP + r] = (u3 > 0.f) ? u3 : 0.2f * u3;
        }
    }
    __syncthreads();

    for (int blk = 0; blk < 2; blk++) {
        // ---- stage 1: weights for BOTH axes, packed bf16x2 ----
        for (int f = tid; f < 12288; f += 512) {
            const int axis = f / 6144;
            const int rem  = f - axis * 6144;
            const int d = rem / 48, jp = rem - d * 48;
            const int s = blk * 2 + axis;
            float2 v;
            if (jp < 16) v = *(const float2*)(Wq  + s * 4096 + d * 32 + jp * 2);
            else         v = *(const float2*)(Wkv + s * 8192 + d * 64 + (jp - 16) * 2);
            (axis ? wpC : wpT)[d * 48 + jp] = pbf(v.x, v.y);
        }
        for (int f = tid; f < 4096; f += 512) {
            const int axis = f >> 11;
            const int rem  = f & 2047;
            const int j = rem >> 6, np = rem & 63;
            const int s = blk * 2 + axis;
            float2 v = *(const float2*)(Wout + s * 4096 + j * 128 + np * 2);
            (axis ? woC : woT)[j * 64 + np] = pbf(v.x, v.y);
        }
        if (tid < 256) {
            const int axis = tid >> 7;
            (axis ? boC : boT)[tid & 127] = Bout[(blk * 2 + axis) * 128 + (tid & 127)];
        }
        __syncthreads();

        // ---- stage 2: qkv for both axes (480 tasks, 8-row x 4-col tiles) ----
        if (tid < 480) {
            const int axis = tid / 240;
            const int t0 = tid - axis * 240;
            const int rg = t0 / 24;
            const int cg = t0 - rg * 24;
            const uint* wp = axis ? wpC : wpT;

            ull acc[4][4];
#pragma unroll
            for (int p = 0; p < 4; p++)
#pragma unroll
                for (int j = 0; j < 4; j++) acc[p][j] = 0ull;

            const float* hb = &hsT[rg * 8];
#pragma unroll 4
            for (int d = 0; d < 128; d++) {
                float2 a0 = *(const float2*)&hb[d * RP + 0];
                float2 a1 = *(const float2*)&hb[d * RP + 2];
                float2 a2 = *(const float2*)&hb[d * RP + 4];
                float2 a3 = *(const float2*)&hb[d * RP + 6];
                uint2 uw = *(const uint2*)&wp[d * 48 + cg * 2];
                float w0 = blo(uw.x), w1 = bhi(uw.x);
                float w2 = blo(uw.y), w3 = bhi(uw.y);
                ull ap0 = pack2(a0.x, a0.y), ap1 = pack2(a1.x, a1.y);
                ull ap2 = pack2(a2.x, a2.y), ap3 = pack2(a3.x, a3.y);
                ull bp0 = pack2(w0, w0), bp1 = pack2(w1, w1);
                ull bp2 = pack2(w2, w2), bp3 = pack2(w3, w3);
                acc[0][0] = ffma2(ap0, bp0, acc[0][0]);
                acc[0][1] = ffma2(ap0, bp1, acc[0][1]);
                acc[0][2] = ffma2(ap0, bp2, acc[0][2]);
                acc[0][3] = ffma2(ap0, bp3, acc[0][3]);
                acc[1][0] = ffma2(ap1, bp0, acc[1][0]);
                acc[1][1] = ffma2(ap1, bp1, acc[1][1]);
                acc[1][2] = ffma2(ap1, bp2, acc[1][2]);
                acc[1][3] = ffma2(ap1, bp3, acc[1][3]);
                acc[2][0] = ffma2(ap2, bp0, acc[2][0]);
                acc[2][1] = ffma2(ap2, bp1, acc[2][1]);
                acc[2][2] = ffma2(ap2, bp2, acc[2][2]);
                acc[2][3] = ffma2(ap2, bp3, acc[2][3]);
                acc[3][0] = ffma2(ap3, bp0, acc[3][0]);
                acc[3][1] = ffma2(ap3, bp1, acc[3][1]);
                acc[3][2] = ffma2(ap3, bp2, acc[3][2]);
                acc[3][3] = ffma2(ap3, bp3, acc[3][3]);
            }
            const int which = cg >> 3;   // 0=q, 1=k, 2=v
            float* dst = axis ? ((which == 0) ? qsC : (which == 1) ? ksC : vsC)
                              : ((which == 0) ? qsT : (which == 1) ? ksT : vsT);
            const int lj = (cg & 7) * 4;
#pragma unroll
            for (int p = 0; p < 4; p++) {
                const int r0 = rg * 8 + 2 * p;
#pragma unroll
                for (int jc = 0; jc < 4; jc++) {
                    float2 v = unpack2(acc[p][jc]);
                    dst[r0 * 32 + lj + jc]       = v.x;
                    dst[(r0 + 1) * 32 + lj + jc] = v.y;
                }
            }
        }
        __syncthreads();

        // ---- stage 3: attention cores, both axes (1280 tasks) ----
        for (int o = tid; o < 1280; o += 512) {
            if (o < 640) {
                // axis T
                const int t  = o % 20;
                const int ch = o / 20;
                const int c  = ch & 3, h = ch >> 2;
                const int r  = t * 4 + c;
                const float* qp = &qsT[r * 32 + h * 4];
                float p[20];
                float mx = -1e30f;
#pragma unroll
                for (int s2 = 0; s2 < 20; s2++) {
                    const float* kp = &ksT[(s2 * 4 + c) * 32 + h * 4];
                    float d = (qp[0]*kp[0] + qp[1]*kp[1] + qp[2]*kp[2] + qp[3]*kp[3]) * 0.5f;
                    p[s2] = d;
                    mx = fmaxf(mx, d);
                }
                float sum = 0.f;
#pragma unroll
                for (int s2 = 0; s2 < 20; s2++) { p[s2] = __expf(p[s2] - mx); sum += p[s2]; }
                float inv = 1.f / sum;
                float o0 = 0.f, o1 = 0.f, o2 = 0.f, o3 = 0.f;
#pragma unroll
                for (int s2 = 0; s2 < 20; s2++) {
                    const float* vp = &vsT[(s2 * 4 + c) * 32 + h * 4];
                    float w = p[s2] * inv;
                    o0 += w * vp[0]; o1 += w * vp[1]; o2 += w * vp[2]; o3 += w * vp[3];
                }
                osTT[(h*4 + 0) * RP + r] = o0;
                osTT[(h*4 + 1) * RP + r] = o1;
                osTT[(h*4 + 2) * RP + r] = o2;
                osTT[(h*4 + 3) * RP + r] = o3;
            } else {
                // axis C
                const int oo = o - 640;
                const int cq = oo & 3;
                const int h  = (oo >> 2) & 7;
                const int t  = oo >> 5;
                const int r  = t * 4 + cq;
                const float* qp = &qsC[r * 32 + h * 4];
                float p[4];
                float mx = -1e30f;
#pragma unroll
                for (int s2 = 0; s2 < 4; s2++) {
                    const float* kp = &ksC[(t * 4 + s2) * 32 + h * 4];
                    float d = (qp[0]*kp[0] + qp[1]*kp[1] + qp[2]*kp[2] + qp[3]*kp[3]) * 0.5f;
                    p[s2] = d;
                    mx = fmaxf(mx, d);
                }
                float sum = 0.f;
#pragma unroll
                for (int s2 = 0; s2 < 4; s2++) { p[s2] = __expf(p[s2] - mx); sum += p[s2]; }
                float inv = 1.f / sum;
                float o0 = 0.f, o1 = 0.f, o2 = 0.f, o3 = 0.f;
#pragma unroll
                for (int s2 = 0; s2 < 4; s2++) {
                    const float* vp = &vsC[(t * 4 + s2) * 32 + h * 4];
                    float w = p[s2] * inv;
                    o0 += w * vp[0]; o1 += w * vp[1]; o2 += w * vp[2]; o3 += w * vp[3];
                }
                osTC[(h*4 + 0) * RP + r] = o0;
                osTC[(h*4 + 1) * RP + r] = o1;
                osTC[(h*4 + 2) * RP + r] = o2;
                osTC[(h*4 + 3) * RP + r] = o3;
            }
        }
        __syncthreads();

        // ---- stage 4: fused out-projection (T + C) + leaky -> hsT ----
        if (tid < 320) {
            const int rg = tid >> 4;          // 0..19 (rows rg*4..+3)
            const int cg = tid & 15;          // cols cg*8..+7
            ull acc[2][8];
#pragma unroll
            for (int p = 0; p < 2; p++)
#pragma unroll
                for (int jc = 0; jc < 8; jc++) acc[p][jc] = 0ull;

            const float* obT = &osTT[rg * 4];
            const float* obC = &osTC[rg * 4];
#pragma unroll
            for (int j = 0; j < 32; j++) {
                float2 t0 = *(const float2*)&obT[j * RP + 0];
                float2 t1 = *(const float2*)&obT[j * RP + 2];
                float2 c0 = *(const float2*)&obC[j * RP + 0];
                float2 c1 = *(const float2*)&obC[j * RP + 2];
                uint4 uT = *(const uint4*)&woT[j * 64 + cg * 4];
                uint4 uC = *(const uint4*)&woC[j * 64 + cg * 4];
                ull apT[2] = { pack2(t0.x, t0.y), pack2(t1.x, t1.y) };
                ull apC[2] = { pack2(c0.x, c0.y), pack2(c1.x, c1.y) };
                float fT[8] = { blo(uT.x), bhi(uT.x), blo(uT.y), bhi(uT.y),
                                blo(uT.z), bhi(uT.z), blo(uT.w), bhi(uT.w) };
                float fC[8] = { blo(uC.x), bhi(uC.x), blo(uC.y), bhi(uC.y),
                                blo(uC.z), bhi(uC.z), blo(uC.w), bhi(uC.w) };
#pragma unroll
                for (int p = 0; p < 2; p++)
#pragma unroll
                    for (int jc = 0; jc < 8; jc++) {
                        acc[p][jc] = ffma2(apT[p], pack2(fT[jc], fT[jc]), acc[p][jc]);
                        acc[p][jc] = ffma2(apC[p], pack2(fC[jc], fC[jc]), acc[p][jc]);
                    }
            }
#pragma unroll
            for (int jc = 0; jc < 8; jc++) {
                const int n = cg * 8 + jc;
                const float bia = boT[n] + boC[n];
#pragma unroll
                for (int p = 0; p < 2; p++) {
                    float2 v = unpack2(acc[p][jc]);
                    const int r0 = rg * 4 + 2 * p;
                    float u0 = v.x + bia;
                    float u1 = v.y + bia;
                    hsT[n * RP + r0]     = (u0 > 0.f) ? u0 : 0.2f * u0;
                    hsT[n * RP + r0 + 1] = (u1 > 0.f) ? u1 : 0.2f * u1;
                }
            }
        }
        __syncthreads();
    }

    // ---- decoder ----
    float acc = 0.f;
    for (int f = tid; f < 10240; f += 512) {
        int r = f >> 7, d = f & 127;
        acc += hsT[d * RP + r] * Wd[f];
    }
#pragma unroll
    for (int off = 16; off; off >>= 1) acc += __shfl_down_sync(0xffffffffu, acc, off);
    if ((tid & 31) == 0) qsT[tid >> 5] = acc;
    __syncthreads();
    if (tid == 0) {
        float s = 0.f;
#pragma unroll
        for (int w = 0; w < 16; w++) s += qsT[w];
        s += bd[0];
        out[b] = 1.f / (1.f + __expf(-s));
    }
}

// ---------------------------------------------------------------------------
// Launch
// ---------------------------------------------------------------------------
extern "C" void kernel_launch(void* const* d_in, const int* in_sizes, int n_in,
                              void* d_out, int out_size)
{
    const float* x     = (const float*)d_in[0];
    const float* W_emb = (const float*)d_in[3];
    const float* b_emb = (const float*)d_in[4];
    const float* Wq    = (const float*)d_in[5];
    const float* Wkv   = (const float*)d_in[6];
    const float* Wout  = (const float*)d_in[7];
    const float* bout  = (const float*)d_in[8];
    const float* W_dec = (const float*)d_in[9];
    const float* b_dec = (const float*)d_in[10];
    float* out = (float*)d_out;

    cudaFuncSetAttribute(emb_mma_kernel, cudaFuncAttributeMaxDynamicSharedMemorySize, EMB_SMEM);
    cudaFuncSetAttribute(mega_kernel, cudaFuncAttributeMaxDynamicSharedMemorySize, MEGA_BYTES);

    dim3 cg(K_TOT / 32, N_TOT / 32);
    conv_w_kernel<<<cg, 256>>>(W_emb);

    dim3 eg(M_TOT / MTILE, KSPLIT);
    emb_mma_kernel<<<eg, 256, EMB_SMEM>>>(x);

    mega_kernel<<<B_, 512, MEGA_BYTES>>>(Wq, Wkv, Wout, bout, b_emb, W_dec, b_dec, out);
}